// round 1
// baseline (speedup 1.0000x reference)
#include <cuda_runtime.h>
#include <cmath>
#include <cstdint>

// Problem constants
#define NN   50000      // nodes
#define EE   800000     // raw edges
#define ETOT 850000     // edges + self loops
#define INC  128        // in channels
#define HID  64         // hidden per head
#define NH   4          // heads
#define HK   256        // NH*HID
#define OUTC 40
#define NLAY 4

// ---------------- device scratch (no allocations allowed) ----------------
__device__ float g_h[(size_t)NN * HID];      // node features (ping layer state)
__device__ float g_xl[(size_t)NN * HK];      // per-layer transformed features [N, H*HID]
__device__ float g_as[(size_t)NN * NH];      // alpha_src per node/head
__device__ float g_ad[(size_t)NN * NH];      // alpha_dst per node/head
__device__ float g_m[(size_t)NN * NH];       // segment max
__device__ float g_den[(size_t)NN * NH];     // segment sum of exp
__device__ float g_aexp[(size_t)ETOT * NH];  // exp(e - m[dst]) per edge/head
__device__ int   g_deg[NN];
__device__ int   g_rowptr[NN + 1];
__device__ int   g_cursor[NN];
__device__ int   g_csrc[ETOT];
__device__ int   g_ceid[ETOT];

// ---------------- helpers ----------------
__device__ __forceinline__ void atomicMaxFloat(float* addr, float value) {
    if (value >= 0.f) atomicMax((int*)addr, __float_as_int(value));
    else              atomicMin((unsigned int*)addr, __float_as_uint(value));
}

__device__ __forceinline__ float lrelu02(float v) { return v > 0.f ? v : 0.2f * v; }

// ---------------- CSR build ----------------
__global__ void hist_kernel(const int* __restrict__ ei) {
    int e = blockIdx.x * blockDim.x + threadIdx.x;
    if (e >= ETOT) return;
    int d = (e < EE) ? ei[EE + e] : (e - EE);
    atomicAdd(&g_deg[d], 1);
}

__global__ void scan_kernel() {
    __shared__ int wsum[32];
    __shared__ int carry;
    int t = threadIdx.x;
    if (t == 0) carry = 0;
    __syncthreads();
    for (int base = 0; base < NN; base += 1024) {
        int v = (base + t < NN) ? g_deg[base + t] : 0;
        int x = v;
        #pragma unroll
        for (int s = 1; s < 32; s <<= 1) {
            int y = __shfl_up_sync(0xFFFFFFFFu, x, s);
            if ((t & 31) >= s) x += y;
        }
        if ((t & 31) == 31) wsum[t >> 5] = x;
        __syncthreads();
        if (t < 32) {
            int y = wsum[t];
            #pragma unroll
            for (int s = 1; s < 32; s <<= 1) {
                int z = __shfl_up_sync(0xFFFFFFFFu, y, s);
                if (t >= s) y += z;
            }
            wsum[t] = y;
        }
        __syncthreads();
        int incl = x + ((t >= 32) ? wsum[(t >> 5) - 1] : 0);
        if (base + t < NN) g_rowptr[base + t] = carry + incl - v;
        __syncthreads();
        if (t == 0) carry += wsum[31];
        __syncthreads();
    }
    if (t == 0) g_rowptr[NN] = carry;
}

__global__ void scatter_kernel(const int* __restrict__ ei) {
    int e = blockIdx.x * blockDim.x + threadIdx.x;
    if (e >= ETOT) return;
    int s, d;
    if (e < EE) { s = ei[e]; d = ei[EE + e]; } else { s = d = e - EE; }
    int pos = atomicAdd(&g_cursor[d], 1);
    g_csrc[pos] = s;
    g_ceid[pos] = e;
}

// ---------------- GEMM (fp32 tiled, 64x64 tile, 256 threads, 4x4 micro) ----------------
__global__ void gemm_tiled(const float* __restrict__ A, const float* __restrict__ B,
                           const float* __restrict__ bias, float* __restrict__ C,
                           int M, int K, int Nc, int act) {
    __shared__ float As[16][68];
    __shared__ float Bs[16][68];
    int t  = threadIdx.x;
    int tx = t & 15, ty = t >> 4;
    int m0 = blockIdx.y << 6;
    int n0 = blockIdx.x << 6;
    float acc[4][4] = {};

    int am = t >> 2;           // 0..63
    int ak = (t & 3) << 2;     // 0,4,8,12
    int bk = t >> 4;           // 0..15
    int bn = (t & 15) << 2;    // 0..60

    for (int k0 = 0; k0 < K; k0 += 16) {
        float4 av = make_float4(0.f, 0.f, 0.f, 0.f);
        int arow = m0 + am;
        if (arow < M) av = *(const float4*)(A + (size_t)arow * K + k0 + ak);
        As[ak + 0][am] = av.x; As[ak + 1][am] = av.y;
        As[ak + 2][am] = av.z; As[ak + 3][am] = av.w;

        float b0 = 0.f, b1 = 0.f, b2 = 0.f, b3 = 0.f;
        {
            const float* bp = B + (size_t)(k0 + bk) * Nc + n0 + bn;
            if (n0 + bn + 3 < Nc) {
                float4 bv = *(const float4*)bp;
                b0 = bv.x; b1 = bv.y; b2 = bv.z; b3 = bv.w;
            } else {
                if (n0 + bn + 0 < Nc) b0 = bp[0];
                if (n0 + bn + 1 < Nc) b1 = bp[1];
                if (n0 + bn + 2 < Nc) b2 = bp[2];
                if (n0 + bn + 3 < Nc) b3 = bp[3];
            }
        }
        Bs[bk][bn + 0] = b0; Bs[bk][bn + 1] = b1;
        Bs[bk][bn + 2] = b2; Bs[bk][bn + 3] = b3;
        __syncthreads();

        #pragma unroll
        for (int kk = 0; kk < 16; kk++) {
            float4 a = *(const float4*)&As[kk][ty << 2];
            float4 b = *(const float4*)&Bs[kk][tx << 2];
            acc[0][0] += a.x * b.x; acc[0][1] += a.x * b.y; acc[0][2] += a.x * b.z; acc[0][3] += a.x * b.w;
            acc[1][0] += a.y * b.x; acc[1][1] += a.y * b.y; acc[1][2] += a.y * b.z; acc[1][3] += a.y * b.w;
            acc[2][0] += a.z * b.x; acc[2][1] += a.z * b.y; acc[2][2] += a.z * b.z; acc[2][3] += a.z * b.w;
            acc[3][0] += a.w * b.x; acc[3][1] += a.w * b.y; acc[3][2] += a.w * b.z; acc[3][3] += a.w * b.w;
        }
        __syncthreads();
    }

    #pragma unroll
    for (int i = 0; i < 4; i++) {
        int r = m0 + (ty << 2) + i;
        if (r >= M) continue;
        #pragma unroll
        for (int j = 0; j < 4; j++) {
            int c = n0 + (tx << 2) + j;
            if (c >= Nc) continue;
            float v = acc[i][j];
            if (bias) v += bias[c];
            if (act) v = v > 0.f ? v : expm1f(v);
            C[(size_t)r * Nc + c] = v;
        }
    }
}

// ---------------- alpha_src / alpha_dst per node-head ----------------
__global__ void alpha_kernel(const float* __restrict__ att_src,
                             const float* __restrict__ att_dst, int layer) {
    int tid = blockIdx.x * blockDim.x + threadIdx.x;
    if (tid >= NN * NH) return;
    int h = tid & 3;
    const float* xr = g_xl + ((size_t)(tid >> 2)) * HK + h * HID;
    const float* as = att_src + layer * HK + h * HID;
    const float* ad = att_dst + layer * HK + h * HID;
    float s1 = 0.f, s2 = 0.f;
    #pragma unroll
    for (int c = 0; c < HID; c += 4) {
        float4 xv = *(const float4*)(xr + c);
        float4 av = *(const float4*)(as + c);
        float4 dv = *(const float4*)(ad + c);
        s1 += xv.x * av.x + xv.y * av.y + xv.z * av.z + xv.w * av.w;
        s2 += xv.x * dv.x + xv.y * dv.y + xv.z * dv.z + xv.w * dv.w;
    }
    g_as[tid] = s1;
    g_ad[tid] = s2;
}

// ---------------- softmax init / edge passes ----------------
__global__ void init_softmax() {
    int i = blockIdx.x * blockDim.x + threadIdx.x;
    if (i >= NN * NH) return;
    g_m[i]   = __int_as_float(0xFF800000u);  // -inf
    g_den[i] = 0.f;
}

__global__ void edge_max(const int* __restrict__ ei) {
    int e = blockIdx.x * blockDim.x + threadIdx.x;
    if (e >= ETOT) return;
    int s, d;
    if (e < EE) { s = ei[e]; d = ei[EE + e]; } else { s = d = e - EE; }
    float4 as = *(const float4*)(g_as + 4 * (size_t)s);
    float4 ad = *(const float4*)(g_ad + 4 * (size_t)d);
    atomicMaxFloat(&g_m[4 * d + 0], lrelu02(as.x + ad.x));
    atomicMaxFloat(&g_m[4 * d + 1], lrelu02(as.y + ad.y));
    atomicMaxFloat(&g_m[4 * d + 2], lrelu02(as.z + ad.z));
    atomicMaxFloat(&g_m[4 * d + 3], lrelu02(as.w + ad.w));
}

__global__ void edge_exp(const int* __restrict__ ei) {
    int e = blockIdx.x * blockDim.x + threadIdx.x;
    if (e >= ETOT) return;
    int s, d;
    if (e < EE) { s = ei[e]; d = ei[EE + e]; } else { s = d = e - EE; }
    float4 as = *(const float4*)(g_as + 4 * (size_t)s);
    float4 ad = *(const float4*)(g_ad + 4 * (size_t)d);
    float4 mv = *(const float4*)(g_m + 4 * (size_t)d);
    float4 ev;
    ev.x = expf(lrelu02(as.x + ad.x) - mv.x);
    ev.y = expf(lrelu02(as.y + ad.y) - mv.y);
    ev.z = expf(lrelu02(as.z + ad.z) - mv.z);
    ev.w = expf(lrelu02(as.w + ad.w) - mv.w);
    *(float4*)(g_aexp + 4 * (size_t)e) = ev;
    atomicAdd(&g_den[4 * d + 0], ev.x);
    atomicAdd(&g_den[4 * d + 1], ev.y);
    atomicAdd(&g_den[4 * d + 2], ev.z);
    atomicAdd(&g_den[4 * d + 3], ev.w);
}

// ---------------- fused aggregation + head-mean + bias + LN + ELU + residual ----------------
__global__ void agg_fused(const float* __restrict__ gat_b,
                          const float* __restrict__ ln_g,
                          const float* __restrict__ ln_b, int layer) {
    int w    = (blockIdx.x * blockDim.x + threadIdx.x) >> 5;
    int lane = threadIdx.x & 31;
    if (w >= NN) return;

    float a00 = 0.f, a01 = 0.f, a10 = 0.f, a11 = 0.f;
    float a20 = 0.f, a21 = 0.f, a30 = 0.f, a31 = 0.f;

    int beg = g_rowptr[w], end = g_rowptr[w + 1];
    for (int i = beg; i < end; i++) {
        int s = g_csrc[i];
        int e = g_ceid[i];
        float4 al = *(const float4*)(g_aexp + 4 * (size_t)e);
        const float* xs = g_xl + (size_t)s * HK;
        a00 += al.x * xs[lane];        a01 += al.x * xs[lane + 32];
        a10 += al.y * xs[64 + lane];   a11 += al.y * xs[64 + lane + 32];
        a20 += al.z * xs[128 + lane];  a21 += al.z * xs[128 + lane + 32];
        a30 += al.w * xs[192 + lane];  a31 += al.w * xs[192 + lane + 32];
    }

    float4 dn = *(const float4*)(g_den + 4 * (size_t)w);
    float i0 = 1.f / (dn.x + 1e-16f), i1 = 1.f / (dn.y + 1e-16f);
    float i2 = 1.f / (dn.z + 1e-16f), i3 = 1.f / (dn.w + 1e-16f);

    float v0 = 0.25f * (a00 * i0 + a10 * i1 + a20 * i2 + a30 * i3) + gat_b[layer * HID + lane];
    float v1 = 0.25f * (a01 * i0 + a11 * i1 + a21 * i2 + a31 * i3) + gat_b[layer * HID + lane + 32];

    // LayerNorm over 64 channels (2 per lane)
    float sum = v0 + v1, sq = v0 * v0 + v1 * v1;
    #pragma unroll
    for (int s = 16; s > 0; s >>= 1) {
        sum += __shfl_xor_sync(0xFFFFFFFFu, sum, s);
        sq  += __shfl_xor_sync(0xFFFFFFFFu, sq, s);
    }
    float mu   = sum * (1.f / 64.f);
    float var  = sq * (1.f / 64.f) - mu * mu;
    float rstd = rsqrtf(var + 1e-5f);

    float gg0 = ln_g[layer * HID + lane], gg1 = ln_g[layer * HID + lane + 32];
    float bb0 = ln_b[layer * HID + lane], bb1 = ln_b[layer * HID + lane + 32];
    v0 = (v0 - mu) * rstd * gg0 + bb0;
    v1 = (v1 - mu) * rstd * gg1 + bb1;
    v0 = v0 > 0.f ? v0 : expm1f(v0);
    v1 = v1 > 0.f ? v1 : expm1f(v1);

    float* hp = g_h + (size_t)w * HID;
    if (layer > 0) { v0 += hp[lane]; v1 += hp[lane + 32]; }
    hp[lane]      = v0;
    hp[lane + 32] = v1;
}

// ---------------- host orchestration ----------------
extern "C" void kernel_launch(void* const* d_in, const int* in_sizes, int n_in,
                              void* d_out, int out_size) {
    const float* x       = (const float*)d_in[0];
    const int*   ei      = (const int*)d_in[1];
    const float* Wi      = (const float*)d_in[2];
    const float* bi      = (const float*)d_in[3];
    const float* lin_W   = (const float*)d_in[4];
    const float* att_src = (const float*)d_in[5];
    const float* att_dst = (const float*)d_in[6];
    const float* gat_b   = (const float*)d_in[7];
    const float* ln_g    = (const float*)d_in[8];
    const float* ln_b    = (const float*)d_in[9];
    const float* Wo      = (const float*)d_in[10];
    const float* bo      = (const float*)d_in[11];
    float* out = (float*)d_out;

    static bool inited = false;
    static float *p_h, *p_xl;
    static int *p_deg, *p_rowptr, *p_cursor;
    if (!inited) {
        cudaGetSymbolAddress((void**)&p_h, g_h);
        cudaGetSymbolAddress((void**)&p_xl, g_xl);
        cudaGetSymbolAddress((void**)&p_deg, g_deg);
        cudaGetSymbolAddress((void**)&p_rowptr, g_rowptr);
        cudaGetSymbolAddress((void**)&p_cursor, g_cursor);
        inited = true;
    }

    const int EB = (ETOT + 255) / 256;
    const int MT = (NN + 63) / 64;  // 782

    // CSR build (per launch; cheap)
    cudaMemsetAsync(p_deg, 0, NN * sizeof(int));
    hist_kernel<<<EB, 256>>>(ei);
    scan_kernel<<<1, 1024>>>();
    cudaMemcpyAsync(p_cursor, p_rowptr, NN * sizeof(int), cudaMemcpyDeviceToDevice);
    scatter_kernel<<<EB, 256>>>(ei);

    // h = elu(x @ Wi + bi)
    gemm_tiled<<<dim3(1, MT), 256>>>(x, Wi, bi, p_h, NN, INC, HID, 1);

    for (int l = 0; l < NLAY; l++) {
        gemm_tiled<<<dim3(HK / 64, MT), 256>>>(p_h, lin_W + (size_t)l * HID * HK,
                                               nullptr, p_xl, NN, HID, HK, 0);
        alpha_kernel<<<(NN * NH + 255) / 256, 256>>>(att_src, att_dst, l);
        init_softmax<<<(NN * NH + 255) / 256, 256>>>();
        edge_max<<<EB, 256>>>(ei);
        edge_exp<<<EB, 256>>>(ei);
        agg_fused<<<(NN + 7) / 8, 256>>>(gat_b, ln_g, ln_b, l);
    }

    // out = h @ Wo + bo
    gemm_tiled<<<dim3(1, MT), 256>>>(p_h, Wo, bo, out, NN, HID, OUTC, 0);
}

// round 2
// speedup vs baseline: 1.4688x; 1.4688x over previous
#include <cuda_runtime.h>
#include <cuda_fp16.h>
#include <cmath>
#include <cstdint>

#define NN   50000
#define EE   800000
#define ETOT 850000
#define INC  128
#define HID  64
#define NH   4
#define HK   256
#define OUTC 40
#define NLAY 4

// ---------------- device scratch ----------------
__device__ float  g_h[(size_t)NN * HID];
__device__ __half g_xl[(size_t)NN * HK];     // fp16 transformed features
__device__ float  g_as[(size_t)NN * NH];
__device__ float  g_ad[(size_t)NN * NH];
__device__ int    g_deg[NN];
__device__ int    g_rowptr[NN + 1];
__device__ int    g_cursor[NN];
__device__ int    g_csrc[ETOT];

// ---------------- CSR build ----------------
__global__ void hist_kernel(const int* __restrict__ ei) {
    int e = blockIdx.x * blockDim.x + threadIdx.x;
    if (e >= ETOT) return;
    int d = (e < EE) ? ei[EE + e] : (e - EE);
    atomicAdd(&g_deg[d], 1);
}

__global__ void scan_kernel() {
    __shared__ int wsum[32];
    __shared__ int carry;
    int t = threadIdx.x;
    if (t == 0) carry = 0;
    __syncthreads();
    for (int base = 0; base < NN; base += 1024) {
        int v = (base + t < NN) ? g_deg[base + t] : 0;
        int x = v;
        #pragma unroll
        for (int s = 1; s < 32; s <<= 1) {
            int y = __shfl_up_sync(0xFFFFFFFFu, x, s);
            if ((t & 31) >= s) x += y;
        }
        if ((t & 31) == 31) wsum[t >> 5] = x;
        __syncthreads();
        if (t < 32) {
            int y = wsum[t];
            #pragma unroll
            for (int s = 1; s < 32; s <<= 1) {
                int z = __shfl_up_sync(0xFFFFFFFFu, y, s);
                if (t >= s) y += z;
            }
            wsum[t] = y;
        }
        __syncthreads();
        int incl = x + ((t >= 32) ? wsum[(t >> 5) - 1] : 0);
        if (base + t < NN) g_rowptr[base + t] = carry + incl - v;
        __syncthreads();
        if (t == 0) carry += wsum[31];
        __syncthreads();
    }
    if (t == 0) g_rowptr[NN] = carry;
}

__global__ void scatter_kernel(const int* __restrict__ ei) {
    int e = blockIdx.x * blockDim.x + threadIdx.x;
    if (e >= ETOT) return;
    int s, d;
    if (e < EE) { s = ei[e]; d = ei[EE + e]; } else { s = d = e - EE; }
    int pos = atomicAdd(&g_cursor[d], 1);
    g_csrc[pos] = s;
}

// ---------------- GEMM: 128x64 tile, 8x4 micro, 256 threads ----------------
// mode: 0 = float store, 1 = float store + ELU, 2 = half store
__global__ void gemm128(const float* __restrict__ A, const float* __restrict__ B,
                        const float* __restrict__ bias, void* __restrict__ Cv,
                        int M, int K, int Nc, int mode) {
    __shared__ float As[16][132];
    __shared__ float Bs[16][72];
    int t  = threadIdx.x;
    int tx = t & 15, ty = t >> 4;
    int m0 = blockIdx.y << 7;
    int n0 = blockIdx.x << 6;
    float acc[8][4] = {};

    for (int k0 = 0; k0 < K; k0 += 16) {
        #pragma unroll
        for (int i = 0; i < 2; i++) {
            int idx = t + i * 256;
            int row = idx >> 2;
            int kc  = (idx & 3) << 2;
            float4 av = make_float4(0.f, 0.f, 0.f, 0.f);
            if (m0 + row < M)
                av = *(const float4*)(A + (size_t)(m0 + row) * K + k0 + kc);
            As[kc + 0][row] = av.x; As[kc + 1][row] = av.y;
            As[kc + 2][row] = av.z; As[kc + 3][row] = av.w;
        }
        {
            int bk = t >> 4, bn = (t & 15) << 2;
            const float* bp = B + (size_t)(k0 + bk) * Nc + n0 + bn;
            float4 bv = make_float4(0.f, 0.f, 0.f, 0.f);
            if (n0 + bn + 3 < Nc) bv = *(const float4*)bp;
            else {
                if (n0 + bn + 0 < Nc) bv.x = bp[0];
                if (n0 + bn + 1 < Nc) bv.y = bp[1];
                if (n0 + bn + 2 < Nc) bv.z = bp[2];
            }
            *(float4*)&Bs[bk][bn] = bv;
        }
        __syncthreads();

        #pragma unroll
        for (int kk = 0; kk < 16; kk++) {
            float4 a0 = *(const float4*)&As[kk][ty << 3];
            float4 a1 = *(const float4*)&As[kk][(ty << 3) + 4];
            float4 b  = *(const float4*)&Bs[kk][tx << 2];
            float av[8] = {a0.x, a0.y, a0.z, a0.w, a1.x, a1.y, a1.z, a1.w};
            #pragma unroll
            for (int i = 0; i < 8; i++) {
                acc[i][0] += av[i] * b.x;
                acc[i][1] += av[i] * b.y;
                acc[i][2] += av[i] * b.z;
                acc[i][3] += av[i] * b.w;
            }
        }
        __syncthreads();
    }

    float bb[4] = {0.f, 0.f, 0.f, 0.f};
    if (bias) {
        #pragma unroll
        for (int j = 0; j < 4; j++) {
            int c = n0 + (tx << 2) + j;
            if (c < Nc) bb[j] = bias[c];
        }
    }
    #pragma unroll
    for (int i = 0; i < 8; i++) {
        int r = m0 + (ty << 3) + i;
        if (r >= M) continue;
        int c = n0 + (tx << 2);
        float v0 = acc[i][0] + bb[0], v1 = acc[i][1] + bb[1];
        float v2 = acc[i][2] + bb[2], v3 = acc[i][3] + bb[3];
        if (mode == 1) {
            v0 = v0 > 0.f ? v0 : expm1f(v0);
            v1 = v1 > 0.f ? v1 : expm1f(v1);
            v2 = v2 > 0.f ? v2 : expm1f(v2);
            v3 = v3 > 0.f ? v3 : expm1f(v3);
        }
        if (mode == 2) {
            __half2* cp = (__half2*)((__half*)Cv + (size_t)r * Nc + c);
            cp[0] = __floats2half2_rn(v0, v1);
            cp[1] = __floats2half2_rn(v2, v3);
        } else {
            float* cf = (float*)Cv + (size_t)r * Nc + c;
            if (c + 3 < Nc) {
                *(float4*)cf = make_float4(v0, v1, v2, v3);
            } else {
                if (c + 0 < Nc) cf[0] = v0;
                if (c + 1 < Nc) cf[1] = v1;
                if (c + 2 < Nc) cf[2] = v2;
            }
        }
    }
}

// ---------------- alpha_src / alpha_dst per node-head (from half xl) ----------------
__global__ void alpha_kernel(const float* __restrict__ att_src,
                             const float* __restrict__ att_dst, int layer) {
    int tid = blockIdx.x * blockDim.x + threadIdx.x;
    if (tid >= NN * NH) return;
    int h = tid & 3;
    int n = tid >> 2;
    const uint4*  xr  = (const uint4*)(g_xl + (size_t)n * HK + h * HID);
    const float4* as4 = (const float4*)(att_src + layer * HK + h * HID);
    const float4* ad4 = (const float4*)(att_dst + layer * HK + h * HID);
    float s1 = 0.f, s2 = 0.f;
    #pragma unroll
    for (int c = 0; c < 8; c++) {
        uint4 r = xr[c];
        __half2* hp = (__half2*)&r;
        float2 f0 = __half22float2(hp[0]);
        float2 f1 = __half22float2(hp[1]);
        float2 f2 = __half22float2(hp[2]);
        float2 f3 = __half22float2(hp[3]);
        float4 a0 = as4[2 * c], a1 = as4[2 * c + 1];
        float4 d0 = ad4[2 * c], d1 = ad4[2 * c + 1];
        s1 += f0.x * a0.x + f0.y * a0.y + f1.x * a0.z + f1.y * a0.w
            + f2.x * a1.x + f2.y * a1.y + f3.x * a1.z + f3.y * a1.w;
        s2 += f0.x * d0.x + f0.y * d0.y + f1.x * d0.z + f1.y * d0.w
            + f2.x * d1.x + f2.y * d1.y + f3.x * d1.z + f3.y * d1.w;
    }
    g_as[tid] = s1;
    g_ad[tid] = s2;
}

// ---------------- fused: softmax(no-max) + aggregation + mean + bias + LN + ELU + residual ----------------
__global__ void agg_fused(const float* __restrict__ gat_b,
                          const float* __restrict__ ln_g,
                          const float* __restrict__ ln_b, int layer) {
    int w    = (blockIdx.x * blockDim.x + threadIdx.x) >> 5;
    int lane = threadIdx.x & 31;
    if (w >= NN) return;
    int hl = lane >> 3;          // head owned by this lane
    int c0 = (lane & 7) << 3;    // first of the 8 channels (within head) this lane owns

    float4 ad4 = *(const float4*)(g_ad + 4 * (size_t)w);
    float ad = hl == 0 ? ad4.x : hl == 1 ? ad4.y : hl == 2 ? ad4.z : ad4.w;

    float acc[8] = {};
    float den = 0.f;
    int beg = g_rowptr[w], end = g_rowptr[w + 1];
    const __half* xb = g_xl;

    for (int i = beg; i < end; i++) {
        int s = g_csrc[i];
        float4 as4 = *(const float4*)(g_as + 4 * (size_t)s);
        float as = hl == 0 ? as4.x : hl == 1 ? as4.y : hl == 2 ? as4.z : as4.w;
        float e = as + ad;
        e = e > 0.f ? e : 0.2f * e;
        float p = __expf(e);     // no max-subtraction needed: e is bounded (see theory)
        den += p;

        float4 raw = *(const float4*)(xb + (size_t)s * HK + (lane << 3));
        __half2* hp = (__half2*)&raw;
        float2 f0 = __half22float2(hp[0]);
        float2 f1 = __half22float2(hp[1]);
        float2 f2 = __half22float2(hp[2]);
        float2 f3 = __half22float2(hp[3]);
        acc[0] += p * f0.x; acc[1] += p * f0.y;
        acc[2] += p * f1.x; acc[3] += p * f1.y;
        acc[4] += p * f2.x; acc[5] += p * f2.y;
        acc[6] += p * f3.x; acc[7] += p * f3.y;
    }

    float inv = 1.f / (den + 1e-16f);
    const float* gb = gat_b + layer * HID + c0;
    #pragma unroll
    for (int j = 0; j < 8; j++) {
        float v = acc[j] * inv;
        v += __shfl_xor_sync(0xFFFFFFFFu, v, 8);   // sum over heads
        v += __shfl_xor_sync(0xFFFFFFFFu, v, 16);
        acc[j] = 0.25f * v + gb[j];
    }

    // LayerNorm over 64 channels (each lane holds 8; 4 replica groups of 8 lanes)
    float sum = 0.f, sq = 0.f;
    #pragma unroll
    for (int j = 0; j < 8; j++) { sum += acc[j]; sq += acc[j] * acc[j]; }
    #pragma unroll
    for (int s = 1; s < 8; s <<= 1) {
        sum += __shfl_xor_sync(0xFFFFFFFFu, sum, s);
        sq  += __shfl_xor_sync(0xFFFFFFFFu, sq, s);
    }
    float mu   = sum * (1.f / 64.f);
    float var  = sq * (1.f / 64.f) - mu * mu;
    float rstd = rsqrtf(var + 1e-5f);

    float4 g0 = *(const float4*)(ln_g + layer * HID + c0);
    float4 g1 = *(const float4*)(ln_g + layer * HID + c0 + 4);
    float4 b0 = *(const float4*)(ln_b + layer * HID + c0);
    float4 b1 = *(const float4*)(ln_b + layer * HID + c0 + 4);
    float gg[8] = {g0.x, g0.y, g0.z, g0.w, g1.x, g1.y, g1.z, g1.w};
    float bv[8] = {b0.x, b0.y, b0.z, b0.w, b1.x, b1.y, b1.z, b1.w};

    float* hp = g_h + (size_t)w * HID + c0;
    float res[8] = {};
    if (layer > 0) {
        float4 r0 = *(const float4*)hp;
        float4 r1 = *(const float4*)(hp + 4);
        res[0] = r0.x; res[1] = r0.y; res[2] = r0.z; res[3] = r0.w;
        res[4] = r1.x; res[5] = r1.y; res[6] = r1.z; res[7] = r1.w;
    }
    float out[8];
    #pragma unroll
    for (int j = 0; j < 8; j++) {
        float v = (acc[j] - mu) * rstd * gg[j] + bv[j];
        v = v > 0.f ? v : expm1f(v);
        out[j] = v + res[j];
    }
    if (lane < 8) {
        *(float4*)hp       = make_float4(out[0], out[1], out[2], out[3]);
        *(float4*)(hp + 4) = make_float4(out[4], out[5], out[6], out[7]);
    }
}

// ---------------- host orchestration ----------------
extern "C" void kernel_launch(void* const* d_in, const int* in_sizes, int n_in,
                              void* d_out, int out_size) {
    const float* x       = (const float*)d_in[0];
    const int*   ei      = (const int*)d_in[1];
    const float* Wi      = (const float*)d_in[2];
    const float* bi      = (const float*)d_in[3];
    const float* lin_W   = (const float*)d_in[4];
    const float* att_src = (const float*)d_in[5];
    const float* att_dst = (const float*)d_in[6];
    const float* gat_b   = (const float*)d_in[7];
    const float* ln_g    = (const float*)d_in[8];
    const float* ln_b    = (const float*)d_in[9];
    const float* Wo      = (const float*)d_in[10];
    const float* bo      = (const float*)d_in[11];
    float* out = (float*)d_out;

    static bool inited = false;
    static float *p_h;
    static __half *p_xl;
    static int *p_deg, *p_rowptr, *p_cursor;
    if (!inited) {
        cudaGetSymbolAddress((void**)&p_h, g_h);
        cudaGetSymbolAddress((void**)&p_xl, g_xl);
        cudaGetSymbolAddress((void**)&p_deg, g_deg);
        cudaGetSymbolAddress((void**)&p_rowptr, g_rowptr);
        cudaGetSymbolAddress((void**)&p_cursor, g_cursor);
        inited = true;
    }

    const int EB = (ETOT + 255) / 256;
    const int MB = (NN + 127) / 128;  // 391

    // CSR build
    cudaMemsetAsync(p_deg, 0, NN * sizeof(int));
    hist_kernel<<<EB, 256>>>(ei);
    scan_kernel<<<1, 1024>>>();
    cudaMemcpyAsync(p_cursor, p_rowptr, NN * sizeof(int), cudaMemcpyDeviceToDevice);
    scatter_kernel<<<EB, 256>>>(ei);

    // h = elu(x @ Wi + bi)
    gemm128<<<dim3(1, MB), 256>>>(x, Wi, bi, p_h, NN, INC, HID, 1);

    for (int l = 0; l < NLAY; l++) {
        gemm128<<<dim3(HK / 64, MB), 256>>>(p_h, lin_W + (size_t)l * HID * HK,
                                            nullptr, p_xl, NN, HID, HK, 2);
        alpha_kernel<<<(NN * NH + 255) / 256, 256>>>(att_src, att_dst, l);
        agg_fused<<<(NN + 7) / 8, 256>>>(gat_b, ln_g, ln_b, l);
    }

    // out = h @ Wo + bo
    gemm128<<<dim3(1, MB), 256>>>(p_h, Wo, bo, out, NN, HID, OUTC, 0);
}

// round 3
// speedup vs baseline: 1.7484x; 1.1904x over previous
#include <cuda_runtime.h>
#include <cuda_fp16.h>
#include <cmath>
#include <cstdint>

#define NN   50000
#define EE   800000
#define ETOT 850000
#define INC  128
#define HID  64
#define NH   4
#define HK   256
#define OUTC 40
#define NLAY 4

// ---------------- device scratch ----------------
__device__ float  g_h[(size_t)NN * HID];
__device__ __half g_hh[(size_t)NN * HID];    // half mirror of h (MMA A operand)
__device__ __half g_xl[(size_t)NN * HK];     // fp16 transformed features
__device__ float  g_as[(size_t)NN * NH];
__device__ float  g_ad[(size_t)NN * NH];
__device__ int    g_deg[NN];
__device__ int    g_rowptr[NN + 1];
__device__ int    g_cursor[NN];
__device__ int    g_csrc[ETOT];

// ---------------- CSR build ----------------
__global__ void hist_kernel(const int* __restrict__ ei) {
    int e = blockIdx.x * blockDim.x + threadIdx.x;
    if (e >= ETOT) return;
    int d = (e < EE) ? ei[EE + e] : (e - EE);
    atomicAdd(&g_deg[d], 1);
}

__global__ void scan_kernel() {
    __shared__ int wsum[32];
    __shared__ int carry;
    int t = threadIdx.x;
    if (t == 0) carry = 0;
    __syncthreads();
    for (int base = 0; base < NN; base += 1024) {
        int v = (base + t < NN) ? g_deg[base + t] : 0;
        int x = v;
        #pragma unroll
        for (int s = 1; s < 32; s <<= 1) {
            int y = __shfl_up_sync(0xFFFFFFFFu, x, s);
            if ((t & 31) >= s) x += y;
        }
        if ((t & 31) == 31) wsum[t >> 5] = x;
        __syncthreads();
        if (t < 32) {
            int y = wsum[t];
            #pragma unroll
            for (int s = 1; s < 32; s <<= 1) {
                int z = __shfl_up_sync(0xFFFFFFFFu, y, s);
                if (t >= s) y += z;
            }
            wsum[t] = y;
        }
        __syncthreads();
        int incl = x + ((t >= 32) ? wsum[(t >> 5) - 1] : 0);
        if (base + t < NN) g_rowptr[base + t] = carry + incl - v;
        __syncthreads();
        if (t == 0) carry += wsum[31];
        __syncthreads();
    }
    if (t == 0) g_rowptr[NN] = carry;
}

__global__ void scatter_kernel(const int* __restrict__ ei) {
    int e = blockIdx.x * blockDim.x + threadIdx.x;
    if (e >= ETOT) return;
    int s, d;
    if (e < EE) { s = ei[e]; d = ei[EE + e]; } else { s = d = e - EE; }
    int pos = atomicAdd(&g_cursor[d], 1);
    g_csrc[pos] = s;
}

// ---------------- fp32 GEMM (input / output layers) ----------------
// mode: 0 = float store, 1 = float store + ELU + half mirror to g_hh
__global__ void gemm128(const float* __restrict__ A, const float* __restrict__ B,
                        const float* __restrict__ bias, void* __restrict__ Cv,
                        int M, int K, int Nc, int mode) {
    __shared__ float As[16][132];
    __shared__ float Bs[16][72];
    int t  = threadIdx.x;
    int tx = t & 15, ty = t >> 4;
    int m0 = blockIdx.y << 7;
    int n0 = blockIdx.x << 6;
    float acc[8][4] = {};

    for (int k0 = 0; k0 < K; k0 += 16) {
        #pragma unroll
        for (int i = 0; i < 2; i++) {
            int idx = t + i * 256;
            int row = idx >> 2;
            int kc  = (idx & 3) << 2;
            float4 av = make_float4(0.f, 0.f, 0.f, 0.f);
            if (m0 + row < M)
                av = *(const float4*)(A + (size_t)(m0 + row) * K + k0 + kc);
            As[kc + 0][row] = av.x; As[kc + 1][row] = av.y;
            As[kc + 2][row] = av.z; As[kc + 3][row] = av.w;
        }
        {
            int bk = t >> 4, bn = (t & 15) << 2;
            const float* bp = B + (size_t)(k0 + bk) * Nc + n0 + bn;
            float4 bv = make_float4(0.f, 0.f, 0.f, 0.f);
            if (n0 + bn + 3 < Nc) bv = *(const float4*)bp;
            else {
                if (n0 + bn + 0 < Nc) bv.x = bp[0];
                if (n0 + bn + 1 < Nc) bv.y = bp[1];
                if (n0 + bn + 2 < Nc) bv.z = bp[2];
            }
            *(float4*)&Bs[bk][bn] = bv;
        }
        __syncthreads();

        #pragma unroll
        for (int kk = 0; kk < 16; kk++) {
            float4 a0 = *(const float4*)&As[kk][ty << 3];
            float4 a1 = *(const float4*)&As[kk][(ty << 3) + 4];
            float4 b  = *(const float4*)&Bs[kk][tx << 2];
            float av[8] = {a0.x, a0.y, a0.z, a0.w, a1.x, a1.y, a1.z, a1.w};
            #pragma unroll
            for (int i = 0; i < 8; i++) {
                acc[i][0] += av[i] * b.x;
                acc[i][1] += av[i] * b.y;
                acc[i][2] += av[i] * b.z;
                acc[i][3] += av[i] * b.w;
            }
        }
        __syncthreads();
    }

    float bb[4] = {0.f, 0.f, 0.f, 0.f};
    if (bias) {
        #pragma unroll
        for (int j = 0; j < 4; j++) {
            int c = n0 + (tx << 2) + j;
            if (c < Nc) bb[j] = bias[c];
        }
    }
    #pragma unroll
    for (int i = 0; i < 8; i++) {
        int r = m0 + (ty << 3) + i;
        if (r >= M) continue;
        int c = n0 + (tx << 2);
        float v0 = acc[i][0] + bb[0], v1 = acc[i][1] + bb[1];
        float v2 = acc[i][2] + bb[2], v3 = acc[i][3] + bb[3];
        if (mode == 1) {
            v0 = v0 > 0.f ? v0 : expm1f(v0);
            v1 = v1 > 0.f ? v1 : expm1f(v1);
            v2 = v2 > 0.f ? v2 : expm1f(v2);
            v3 = v3 > 0.f ? v3 : expm1f(v3);
        }
        float* cf = (float*)Cv + (size_t)r * Nc + c;
        if (c + 3 < Nc) {
            *(float4*)cf = make_float4(v0, v1, v2, v3);
        } else {
            if (c + 0 < Nc) cf[0] = v0;
            if (c + 1 < Nc) cf[1] = v1;
            if (c + 2 < Nc) cf[2] = v2;
        }
        if (mode == 1) {
            __half2* hp = (__half2*)(g_hh + (size_t)r * HID + c);
            hp[0] = __floats2half2_rn(v0, v1);
            hp[1] = __floats2half2_rn(v2, v3);
        }
    }
}

// ---------------- tensor-core layer GEMM: xl = h @ W  (M x 64 x 256) ----------------
// Grid: (NH, ceil(NN/128)); block 256 threads (8 warps, 4x2 warp tiles of 32x32).
// A = g_hh [NN,64] half; B = lin_W[l] [64,256] fp32 -> half; C -> g_xl [NN,256] half.
__global__ void gemm_mma(const float* __restrict__ W, int layer) {
    __shared__ alignas(16) __half Asm[128 * 64];  // row 128B, chunk-swizzled
    __shared__ alignas(16) __half Bsm[64 * 64];   // row(k) 128B, chunk-swizzled

    const float* Wl = W + (size_t)layer * HID * HK;
    int t  = threadIdx.x;
    int m0 = blockIdx.y << 7;
    int n0 = blockIdx.x << 6;

    // Load A: 128 rows x 8 chunks(16B); 1024 chunks / 256 threads = 4 each
    #pragma unroll
    for (int i = 0; i < 4; i++) {
        int cid = t + i * 256;
        int r = cid >> 3, c = cid & 7;
        uint4 v = make_uint4(0, 0, 0, 0);
        if (m0 + r < NN)
            v = *(const uint4*)(g_hh + (size_t)(m0 + r) * HID + (c << 3));
        *(uint4*)(Asm + r * 64 + ((c ^ (r & 7)) << 3)) = v;
    }
    // Load B: 64 k-rows x 8 chunks; 512 chunks / 256 = 2 each; convert fp32->half
    #pragma unroll
    for (int i = 0; i < 2; i++) {
        int cid = t + i * 256;
        int k = cid >> 3, c = cid & 7;
        const float* wp = Wl + (size_t)k * HK + n0 + (c << 3);
        float4 w0 = *(const float4*)wp;
        float4 w1 = *(const float4*)(wp + 4);
        __half2 h2[4];
        h2[0] = __floats2half2_rn(w0.x, w0.y);
        h2[1] = __floats2half2_rn(w0.z, w0.w);
        h2[2] = __floats2half2_rn(w1.x, w1.y);
        h2[3] = __floats2half2_rn(w1.z, w1.w);
        *(uint4*)(Bsm + k * 64 + ((c ^ (k & 7)) << 3)) = *(uint4*)h2;
    }
    __syncthreads();

    int wid = t >> 5, lane = t & 31;
    int wm = (wid & 3) << 5;   // warp row base (0,32,64,96)
    int wn = (wid >> 2) << 5;  // warp col base (0,32)

    float c[2][4][4] = {};

    #pragma unroll
    for (int ks = 0; ks < 4; ks++) {
        // A fragments: 2 m16 tiles
        uint32_t a[2][4];
        #pragma unroll
        for (int mt = 0; mt < 2; mt++) {
            int row = wm + (mt << 4) + (lane & 15);
            int chunk = (ks << 1) + (lane >> 4);
            uint32_t addr = (uint32_t)__cvta_generic_to_shared(
                Asm + row * 64 + ((chunk ^ (row & 7)) << 3));
            asm volatile("ldmatrix.sync.aligned.m8n8.x4.shared.b16 {%0,%1,%2,%3}, [%4];"
                         : "=r"(a[mt][0]), "=r"(a[mt][1]), "=r"(a[mt][2]), "=r"(a[mt][3])
                         : "r"(addr));
        }
        // B fragments: 4 n8 tiles via 2 x4.trans loads
        uint32_t b[4][2];
        #pragma unroll
        for (int nt2 = 0; nt2 < 2; nt2++) {
            int krow = (ks << 4) + (lane & 15);
            int nchunk = ((wn + (nt2 << 4)) >> 3) + (lane >> 4);
            uint32_t addr = (uint32_t)__cvta_generic_to_shared(
                Bsm + krow * 64 + ((nchunk ^ (krow & 7)) << 3));
            uint32_t r0, r1, r2, r3;
            asm volatile("ldmatrix.sync.aligned.m8n8.x4.trans.shared.b16 {%0,%1,%2,%3}, [%4];"
                         : "=r"(r0), "=r"(r1), "=r"(r2), "=r"(r3)
                         : "r"(addr));
            b[nt2 * 2 + 0][0] = r0; b[nt2 * 2 + 0][1] = r1;
            b[nt2 * 2 + 1][0] = r2; b[nt2 * 2 + 1][1] = r3;
        }
        #pragma unroll
        for (int mt = 0; mt < 2; mt++)
            #pragma unroll
            for (int nt = 0; nt < 4; nt++)
                asm volatile(
                    "mma.sync.aligned.m16n8k16.row.col.f32.f16.f16.f32 "
                    "{%0,%1,%2,%3},{%4,%5,%6,%7},{%8,%9},{%0,%1,%2,%3};"
                    : "+f"(c[mt][nt][0]), "+f"(c[mt][nt][1]),
                      "+f"(c[mt][nt][2]), "+f"(c[mt][nt][3])
                    : "r"(a[mt][0]), "r"(a[mt][1]), "r"(a[mt][2]), "r"(a[mt][3]),
                      "r"(b[nt][0]), "r"(b[nt][1]));
    }

    // Epilogue: half store to g_xl
    int rg = lane >> 2, cg = (lane & 3) << 1;
    #pragma unroll
    for (int mt = 0; mt < 2; mt++) {
        int r0 = m0 + wm + (mt << 4) + rg;
        #pragma unroll
        for (int nt = 0; nt < 4; nt++) {
            int col = n0 + wn + (nt << 3) + cg;
            if (r0 < NN)
                *(__half2*)(g_xl + (size_t)r0 * HK + col) =
                    __floats2half2_rn(c[mt][nt][0], c[mt][nt][1]);
            if (r0 + 8 < NN)
                *(__half2*)(g_xl + (size_t)(r0 + 8) * HK + col) =
                    __floats2half2_rn(c[mt][nt][2], c[mt][nt][3]);
        }
    }
}

// ---------------- alpha_src / alpha_dst per node-head (from half xl) ----------------
__global__ void alpha_kernel(const float* __restrict__ att_src,
                             const float* __restrict__ att_dst, int layer) {
    int tid = blockIdx.x * blockDim.x + threadIdx.x;
    if (tid >= NN * NH) return;
    int h = tid & 3;
    int n = tid >> 2;
    const uint4*  xr  = (const uint4*)(g_xl + (size_t)n * HK + h * HID);
    const float4* as4 = (const float4*)(att_src + layer * HK + h * HID);
    const float4* ad4 = (const float4*)(att_dst + layer * HK + h * HID);
    float s1 = 0.f, s2 = 0.f;
    #pragma unroll
    for (int c = 0; c < 8; c++) {
        uint4 r = xr[c];
        __half2* hp = (__half2*)&r;
        float2 f0 = __half22float2(hp[0]);
        float2 f1 = __half22float2(hp[1]);
        float2 f2 = __half22float2(hp[2]);
        float2 f3 = __half22float2(hp[3]);
        float4 a0 = as4[2 * c], a1 = as4[2 * c + 1];
        float4 d0 = ad4[2 * c], d1 = ad4[2 * c + 1];
        s1 += f0.x * a0.x + f0.y * a0.y + f1.x * a0.z + f1.y * a0.w
            + f2.x * a1.x + f2.y * a1.y + f3.x * a1.z + f3.y * a1.w;
        s2 += f0.x * d0.x + f0.y * d0.y + f1.x * d0.z + f1.y * d0.w
            + f2.x * d1.x + f2.y * d1.y + f3.x * d1.z + f3.y * d1.w;
    }
    g_as[tid] = s1;
    g_ad[tid] = s2;
}

// ---------------- fused: softmax + aggregation + mean + bias + LN + ELU + residual ----------------
__global__ void agg_fused(const float* __restrict__ gat_b,
                          const float* __restrict__ ln_g,
                          const float* __restrict__ ln_b, int layer) {
    int w    = (blockIdx.x * blockDim.x + threadIdx.x) >> 5;
    int lane = threadIdx.x & 31;
    if (w >= NN) return;
    int hl = lane >> 3;
    int c0 = (lane & 7) << 3;

    float4 ad4 = *(const float4*)(g_ad + 4 * (size_t)w);
    float ad = hl == 0 ? ad4.x : hl == 1 ? ad4.y : hl == 2 ? ad4.z : ad4.w;

    float acc[8] = {};
    float den = 0.f;
    int beg = g_rowptr[w], end = g_rowptr[w + 1];
    const __half* xb = g_xl;

    for (int i = beg; i < end; i++) {
        int s = g_csrc[i];
        float4 as4 = *(const float4*)(g_as + 4 * (size_t)s);
        float as = hl == 0 ? as4.x : hl == 1 ? as4.y : hl == 2 ? as4.z : as4.w;
        float e = as + ad;
        e = e > 0.f ? e : 0.2f * e;
        float p = __expf(e);
        den += p;

        float4 raw = *(const float4*)(xb + (size_t)s * HK + (lane << 3));
        __half2* hp = (__half2*)&raw;
        float2 f0 = __half22float2(hp[0]);
        float2 f1 = __half22float2(hp[1]);
        float2 f2 = __half22float2(hp[2]);
        float2 f3 = __half22float2(hp[3]);
        acc[0] += p * f0.x; acc[1] += p * f0.y;
        acc[2] += p * f1.x; acc[3] += p * f1.y;
        acc[4] += p * f2.x; acc[5] += p * f2.y;
        acc[6] += p * f3.x; acc[7] += p * f3.y;
    }

    float inv = 1.f / (den + 1e-16f);
    const float* gb = gat_b + layer * HID + c0;
    #pragma unroll
    for (int j = 0; j < 8; j++) {
        float v = acc[j] * inv;
        v += __shfl_xor_sync(0xFFFFFFFFu, v, 8);
        v += __shfl_xor_sync(0xFFFFFFFFu, v, 16);
        acc[j] = 0.25f * v + gb[j];
    }

    float sum = 0.f, sq = 0.f;
    #pragma unroll
    for (int j = 0; j < 8; j++) { sum += acc[j]; sq += acc[j] * acc[j]; }
    #pragma unroll
    for (int s = 1; s < 8; s <<= 1) {
        sum += __shfl_xor_sync(0xFFFFFFFFu, sum, s);
        sq  += __shfl_xor_sync(0xFFFFFFFFu, sq, s);
    }
    float mu   = sum * (1.f / 64.f);
    float var  = sq * (1.f / 64.f) - mu * mu;
    float rstd = rsqrtf(var + 1e-5f);

    float4 g0 = *(const float4*)(ln_g + layer * HID + c0);
    float4 g1 = *(const float4*)(ln_g + layer * HID + c0 + 4);
    float4 b0 = *(const float4*)(ln_b + layer * HID + c0);
    float4 b1 = *(const float4*)(ln_b + layer * HID + c0 + 4);
    float gg[8] = {g0.x, g0.y, g0.z, g0.w, g1.x, g1.y, g1.z, g1.w};
    float bv[8] = {b0.x, b0.y, b0.z, b0.w, b1.x, b1.y, b1.z, b1.w};

    float* hp = g_h + (size_t)w * HID + c0;
    float res[8] = {};
    if (layer > 0) {
        float4 r0 = *(const float4*)hp;
        float4 r1 = *(const float4*)(hp + 4);
        res[0] = r0.x; res[1] = r0.y; res[2] = r0.z; res[3] = r0.w;
        res[4] = r1.x; res[5] = r1.y; res[6] = r1.z; res[7] = r1.w;
    }
    float out[8];
    #pragma unroll
    for (int j = 0; j < 8; j++) {
        float v = (acc[j] - mu) * rstd * gg[j] + bv[j];
        v = v > 0.f ? v : expm1f(v);
        out[j] = v + res[j];
    }
    if (lane < 8) {
        *(float4*)hp       = make_float4(out[0], out[1], out[2], out[3]);
        *(float4*)(hp + 4) = make_float4(out[4], out[5], out[6], out[7]);
        __half2 h2[4];
        h2[0] = __floats2half2_rn(out[0], out[1]);
        h2[1] = __floats2half2_rn(out[2], out[3]);
        h2[2] = __floats2half2_rn(out[4], out[5]);
        h2[3] = __floats2half2_rn(out[6], out[7]);
        *(uint4*)(g_hh + (size_t)w * HID + c0) = *(uint4*)h2;
    }
}

// ---------------- host orchestration ----------------
extern "C" void kernel_launch(void* const* d_in, const int* in_sizes, int n_in,
                              void* d_out, int out_size) {
    const float* x       = (const float*)d_in[0];
    const int*   ei      = (const int*)d_in[1];
    const float* Wi      = (const float*)d_in[2];
    const float* bi      = (const float*)d_in[3];
    const float* lin_W   = (const float*)d_in[4];
    const float* att_src = (const float*)d_in[5];
    const float* att_dst = (const float*)d_in[6];
    const float* gat_b   = (const float*)d_in[7];
    const float* ln_g    = (const float*)d_in[8];
    const float* ln_b    = (const float*)d_in[9];
    const float* Wo      = (const float*)d_in[10];
    const float* bo      = (const float*)d_in[11];
    float* out = (float*)d_out;

    static bool inited = false;
    static float *p_h;
    static int *p_deg, *p_rowptr, *p_cursor;
    if (!inited) {
        cudaGetSymbolAddress((void**)&p_h, g_h);
        cudaGetSymbolAddress((void**)&p_deg, g_deg);
        cudaGetSymbolAddress((void**)&p_rowptr, g_rowptr);
        cudaGetSymbolAddress((void**)&p_cursor, g_cursor);
        inited = true;
    }

    const int EB = (ETOT + 255) / 256;
    const int MB = (NN + 127) / 128;  // 391

    // CSR build
    cudaMemsetAsync(p_deg, 0, NN * sizeof(int));
    hist_kernel<<<EB, 256>>>(ei);
    scan_kernel<<<1, 1024>>>();
    cudaMemcpyAsync(p_cursor, p_rowptr, NN * sizeof(int), cudaMemcpyDeviceToDevice);
    scatter_kernel<<<EB, 256>>>(ei);

    // h = elu(x @ Wi + bi)  (also writes g_hh half mirror)
    gemm128<<<dim3(1, MB), 256>>>(x, Wi, bi, p_h, NN, INC, HID, 1);

    for (int l = 0; l < NLAY; l++) {
        gemm_mma<<<dim3(NH, MB), 256>>>(lin_W, l);
        alpha_kernel<<<(NN * NH + 255) / 256, 256>>>(att_src, att_dst, l);
        agg_fused<<<(NN + 7) / 8, 256>>>(gat_b, ln_g, ln_b, l);
    }

    // out = h @ Wo + bo
    gemm128<<<dim3(1, MB), 256>>>(p_h, Wo, bo, out, NN, HID, OUTC, 0);
}

// round 4
// speedup vs baseline: 2.1256x; 1.2158x over previous
#include <cuda_runtime.h>
#include <cuda_fp16.h>
#include <cmath>
#include <cstdint>

#define NN   50000
#define EE   800000
#define ETOT 850000
#define INC  128
#define HID  64
#define NH   4
#define HK   256
#define OUTC 40
#define NLAY 4

// ---------------- device scratch ----------------
__device__ float  g_h[(size_t)NN * HID];
__device__ __half g_hh[(size_t)NN * HID];    // half mirror of h (MMA A operand)
__device__ __half g_xl[(size_t)NN * HK];     // fp16 transformed features
__device__ float  g_as[(size_t)NN * NH];
__device__ float  g_ad[(size_t)NN * NH];
__device__ float  g_wa[NLAY * 8 * HID];      // projected attention vectors
__device__ int    g_deg[NN];
__device__ int    g_rowptr[NN + 1];
__device__ int    g_cursor[NN];
__device__ int    g_csrc[ETOT];

// ---------------- CSR build ----------------
__global__ void hist_kernel(const int* __restrict__ ei) {
    int e = blockIdx.x * blockDim.x + threadIdx.x;
    if (e >= ETOT) return;
    int d = (e < EE) ? ei[EE + e] : (e - EE);
    atomicAdd(&g_deg[d], 1);
}

__global__ void scan_kernel() {
    __shared__ int wsum[32];
    __shared__ int carry;
    int t = threadIdx.x;
    if (t == 0) carry = 0;
    __syncthreads();
    for (int base = 0; base < NN; base += 4096) {
        int i0 = base + t * 4;
        int4 v = make_int4(0, 0, 0, 0);
        if (i0 + 3 < NN) v = *(const int4*)(g_deg + i0);
        else {
            if (i0 + 0 < NN) v.x = g_deg[i0 + 0];
            if (i0 + 1 < NN) v.y = g_deg[i0 + 1];
            if (i0 + 2 < NN) v.z = g_deg[i0 + 2];
            if (i0 + 3 < NN) v.w = g_deg[i0 + 3];
        }
        int tot = v.x + v.y + v.z + v.w;
        int x = tot;
        #pragma unroll
        for (int s = 1; s < 32; s <<= 1) {
            int y = __shfl_up_sync(0xFFFFFFFFu, x, s);
            if ((t & 31) >= s) x += y;
        }
        if ((t & 31) == 31) wsum[t >> 5] = x;
        __syncthreads();
        if (t < 32) {
            int y = wsum[t];
            #pragma unroll
            for (int s = 1; s < 32; s <<= 1) {
                int z = __shfl_up_sync(0xFFFFFFFFu, y, s);
                if (t >= s) y += z;
            }
            wsum[t] = y;
        }
        __syncthreads();
        int excl = carry + x - tot + ((t >= 32) ? wsum[(t >> 5) - 1] : 0);
        if (i0 + 3 < NN) {
            *(int4*)(g_rowptr + i0) =
                make_int4(excl, excl + v.x, excl + v.x + v.y, excl + v.x + v.y + v.z);
        } else {
            if (i0 + 0 < NN) g_rowptr[i0 + 0] = excl;
            if (i0 + 1 < NN) g_rowptr[i0 + 1] = excl + v.x;
            if (i0 + 2 < NN) g_rowptr[i0 + 2] = excl + v.x + v.y;
            if (i0 + 3 < NN) g_rowptr[i0 + 3] = excl + v.x + v.y + v.z;
        }
        __syncthreads();
        if (t == 0) carry += wsum[31];
        __syncthreads();
    }
    if (t == 0) g_rowptr[NN] = carry;
}

__global__ void scatter_kernel(const int* __restrict__ ei) {
    int e = blockIdx.x * blockDim.x + threadIdx.x;
    if (e >= ETOT) return;
    int s, d;
    if (e < EE) { s = ei[e]; d = ei[EE + e]; } else { s = d = e - EE; }
    int pos = atomicAdd(&g_cursor[d], 1);
    g_csrc[pos] = s;
}

// ---------------- projected attention vectors: w~[l][v][k] ----------------
// v in 0..3: src heads; 4..7: dst heads.  w~ = W[:, h*64:(h+1)*64] @ att[h]
__global__ void att_proj_kernel(const float* __restrict__ lin_W,
                                const float* __restrict__ att_src,
                                const float* __restrict__ att_dst) {
    int tid = blockIdx.x * blockDim.x + threadIdx.x;
    if (tid >= NLAY * 8 * HID) return;
    int k = tid & 63;
    int v = (tid >> 6) & 7;
    int l = tid >> 9;
    int h = v & 3;
    const float* att  = (v < 4) ? att_src : att_dst;
    const float* wrow = lin_W + (size_t)l * HID * HK + (size_t)k * HK + h * HID;
    const float* arow = att + l * HK + h * HID;
    float s = 0.f;
    #pragma unroll
    for (int c = 0; c < HID; c++) s += wrow[c] * arow[c];
    g_wa[tid] = s;
}

// ---------------- fp32 GEMM (input / output layers) ----------------
// mode: 0 = float store, 1 = float store + ELU + half mirror to g_hh
__global__ void gemm128(const float* __restrict__ A, const float* __restrict__ B,
                        const float* __restrict__ bias, void* __restrict__ Cv,
                        int M, int K, int Nc, int mode) {
    __shared__ float As[16][132];
    __shared__ float Bs[16][72];
    int t  = threadIdx.x;
    int tx = t & 15, ty = t >> 4;
    int m0 = blockIdx.y << 7;
    int n0 = blockIdx.x << 6;
    float acc[8][4] = {};

    for (int k0 = 0; k0 < K; k0 += 16) {
        #pragma unroll
        for (int i = 0; i < 2; i++) {
            int idx = t + i * 256;
            int row = idx >> 2;
            int kc  = (idx & 3) << 2;
            float4 av = make_float4(0.f, 0.f, 0.f, 0.f);
            if (m0 + row < M)
                av = *(const float4*)(A + (size_t)(m0 + row) * K + k0 + kc);
            As[kc + 0][row] = av.x; As[kc + 1][row] = av.y;
            As[kc + 2][row] = av.z; As[kc + 3][row] = av.w;
        }
        {
            int bk = t >> 4, bn = (t & 15) << 2;
            const float* bp = B + (size_t)(k0 + bk) * Nc + n0 + bn;
            float4 bv = make_float4(0.f, 0.f, 0.f, 0.f);
            if (n0 + bn + 3 < Nc) bv = *(const float4*)bp;
            else {
                if (n0 + bn + 0 < Nc) bv.x = bp[0];
                if (n0 + bn + 1 < Nc) bv.y = bp[1];
                if (n0 + bn + 2 < Nc) bv.z = bp[2];
            }
            *(float4*)&Bs[bk][bn] = bv;
        }
        __syncthreads();

        #pragma unroll
        for (int kk = 0; kk < 16; kk++) {
            float4 a0 = *(const float4*)&As[kk][ty << 3];
            float4 a1 = *(const float4*)&As[kk][(ty << 3) + 4];
            float4 b  = *(const float4*)&Bs[kk][tx << 2];
            float av[8] = {a0.x, a0.y, a0.z, a0.w, a1.x, a1.y, a1.z, a1.w};
            #pragma unroll
            for (int i = 0; i < 8; i++) {
                acc[i][0] += av[i] * b.x;
                acc[i][1] += av[i] * b.y;
                acc[i][2] += av[i] * b.z;
                acc[i][3] += av[i] * b.w;
            }
        }
        __syncthreads();
    }

    float bb[4] = {0.f, 0.f, 0.f, 0.f};
    if (bias) {
        #pragma unroll
        for (int j = 0; j < 4; j++) {
            int c = n0 + (tx << 2) + j;
            if (c < Nc) bb[j] = bias[c];
        }
    }
    #pragma unroll
    for (int i = 0; i < 8; i++) {
        int r = m0 + (ty << 3) + i;
        if (r >= M) continue;
        int c = n0 + (tx << 2);
        float v0 = acc[i][0] + bb[0], v1 = acc[i][1] + bb[1];
        float v2 = acc[i][2] + bb[2], v3 = acc[i][3] + bb[3];
        if (mode == 1) {
            v0 = v0 > 0.f ? v0 : expm1f(v0);
            v1 = v1 > 0.f ? v1 : expm1f(v1);
            v2 = v2 > 0.f ? v2 : expm1f(v2);
            v3 = v3 > 0.f ? v3 : expm1f(v3);
        }
        float* cf = (float*)Cv + (size_t)r * Nc + c;
        if (c + 3 < Nc) {
            *(float4*)cf = make_float4(v0, v1, v2, v3);
        } else {
            if (c + 0 < Nc) cf[0] = v0;
            if (c + 1 < Nc) cf[1] = v1;
            if (c + 2 < Nc) cf[2] = v2;
        }
        if (mode == 1) {
            __half2* hp = (__half2*)(g_hh + (size_t)r * HID + c);
            hp[0] = __floats2half2_rn(v0, v1);
            hp[1] = __floats2half2_rn(v2, v3);
        }
    }
}

// ---------------- tensor-core layer GEMM: xl = h @ W  (M x 64 x 256) ----------------
__global__ void gemm_mma(const float* __restrict__ W, int layer) {
    __shared__ alignas(16) __half Asm[128 * 64];
    __shared__ alignas(16) __half Bsm[64 * 64];

    const float* Wl = W + (size_t)layer * HID * HK;
    int t  = threadIdx.x;
    int m0 = blockIdx.y << 7;
    int n0 = blockIdx.x << 6;

    #pragma unroll
    for (int i = 0; i < 4; i++) {
        int cid = t + i * 256;
        int r = cid >> 3, c = cid & 7;
        uint4 v = make_uint4(0, 0, 0, 0);
        if (m0 + r < NN)
            v = *(const uint4*)(g_hh + (size_t)(m0 + r) * HID + (c << 3));
        *(uint4*)(Asm + r * 64 + ((c ^ (r & 7)) << 3)) = v;
    }
    #pragma unroll
    for (int i = 0; i < 2; i++) {
        int cid = t + i * 256;
        int k = cid >> 3, c = cid & 7;
        const float* wp = Wl + (size_t)k * HK + n0 + (c << 3);
        float4 w0 = *(const float4*)wp;
        float4 w1 = *(const float4*)(wp + 4);
        __half2 h2[4];
        h2[0] = __floats2half2_rn(w0.x, w0.y);
        h2[1] = __floats2half2_rn(w0.z, w0.w);
        h2[2] = __floats2half2_rn(w1.x, w1.y);
        h2[3] = __floats2half2_rn(w1.z, w1.w);
        *(uint4*)(Bsm + k * 64 + ((c ^ (k & 7)) << 3)) = *(uint4*)h2;
    }
    __syncthreads();

    int wid = t >> 5, lane = t & 31;
    int wm = (wid & 3) << 5;
    int wn = (wid >> 2) << 5;

    float c[2][4][4] = {};

    #pragma unroll
    for (int ks = 0; ks < 4; ks++) {
        uint32_t a[2][4];
        #pragma unroll
        for (int mt = 0; mt < 2; mt++) {
            int row = wm + (mt << 4) + (lane & 15);
            int chunk = (ks << 1) + (lane >> 4);
            uint32_t addr = (uint32_t)__cvta_generic_to_shared(
                Asm + row * 64 + ((chunk ^ (row & 7)) << 3));
            asm volatile("ldmatrix.sync.aligned.m8n8.x4.shared.b16 {%0,%1,%2,%3}, [%4];"
                         : "=r"(a[mt][0]), "=r"(a[mt][1]), "=r"(a[mt][2]), "=r"(a[mt][3])
                         : "r"(addr));
        }
        uint32_t b[4][2];
        #pragma unroll
        for (int nt2 = 0; nt2 < 2; nt2++) {
            int krow = (ks << 4) + (lane & 15);
            int nchunk = ((wn + (nt2 << 4)) >> 3) + (lane >> 4);
            uint32_t addr = (uint32_t)__cvta_generic_to_shared(
                Bsm + krow * 64 + ((nchunk ^ (krow & 7)) << 3));
            uint32_t r0, r1, r2, r3;
            asm volatile("ldmatrix.sync.aligned.m8n8.x4.trans.shared.b16 {%0,%1,%2,%3}, [%4];"
                         : "=r"(r0), "=r"(r1), "=r"(r2), "=r"(r3)
                         : "r"(addr));
            b[nt2 * 2 + 0][0] = r0; b[nt2 * 2 + 0][1] = r1;
            b[nt2 * 2 + 1][0] = r2; b[nt2 * 2 + 1][1] = r3;
        }
        #pragma unroll
        for (int mt = 0; mt < 2; mt++)
            #pragma unroll
            for (int nt = 0; nt < 4; nt++)
                asm volatile(
                    "mma.sync.aligned.m16n8k16.row.col.f32.f16.f16.f32 "
                    "{%0,%1,%2,%3},{%4,%5,%6,%7},{%8,%9},{%0,%1,%2,%3};"
                    : "+f"(c[mt][nt][0]), "+f"(c[mt][nt][1]),
                      "+f"(c[mt][nt][2]), "+f"(c[mt][nt][3])
                    : "r"(a[mt][0]), "r"(a[mt][1]), "r"(a[mt][2]), "r"(a[mt][3]),
                      "r"(b[nt][0]), "r"(b[nt][1]));
    }

    int rg = lane >> 2, cg = (lane & 3) << 1;
    #pragma unroll
    for (int mt = 0; mt < 2; mt++) {
        int r0 = m0 + wm + (mt << 4) + rg;
        #pragma unroll
        for (int nt = 0; nt < 4; nt++) {
            int col = n0 + wn + (nt << 3) + cg;
            if (r0 < NN)
                *(__half2*)(g_xl + (size_t)r0 * HK + col) =
                    __floats2half2_rn(c[mt][nt][0], c[mt][nt][1]);
            if (r0 + 8 < NN)
                *(__half2*)(g_xl + (size_t)(r0 + 8) * HK + col) =
                    __floats2half2_rn(c[mt][nt][2], c[mt][nt][3]);
        }
    }
}

// ---------------- alphas from g_hh and projected vectors ----------------
__global__ void alpha2_kernel(int layer) {
    __shared__ float wa[8][64];
    int t = threadIdx.x;
    #pragma unroll
    for (int i = 0; i < 2; i++)
        ((float*)wa)[t + i * 256] = g_wa[layer * 512 + t + i * 256];
    __syncthreads();
    int n = blockIdx.x * 256 + t;
    if (n >= NN) return;
    const uint4* hp = (const uint4*)(g_hh + (size_t)n * HID);
    float r[8] = {};
    #pragma unroll
    for (int cc = 0; cc < 8; cc++) {
        uint4 raw = hp[cc];
        __half2* h2 = (__half2*)&raw;
        float f[8];
        float2 t0 = __half22float2(h2[0]); f[0] = t0.x; f[1] = t0.y;
        float2 t1 = __half22float2(h2[1]); f[2] = t1.x; f[3] = t1.y;
        float2 t2 = __half22float2(h2[2]); f[4] = t2.x; f[5] = t2.y;
        float2 t3 = __half22float2(h2[3]); f[6] = t3.x; f[7] = t3.y;
        #pragma unroll
        for (int v = 0; v < 8; v++) {
            #pragma unroll
            for (int j = 0; j < 8; j++)
                r[v] += f[j] * wa[v][cc * 8 + j];
        }
    }
    *(float4*)(g_as + 4 * (size_t)n) = make_float4(r[0], r[1], r[2], r[3]);
    *(float4*)(g_ad + 4 * (size_t)n) = make_float4(r[4], r[5], r[6], r[7]);
}

// ---------------- fused aggregation epilogue ----------------
__device__ __forceinline__ float head_sel(float4 v, int hl) {
    return hl == 0 ? v.x : hl == 1 ? v.y : hl == 2 ? v.z : v.w;
}

__global__ void agg_fused(const float* __restrict__ gat_b,
                          const float* __restrict__ ln_g,
                          const float* __restrict__ ln_b, int layer) {
    int w    = (blockIdx.x * blockDim.x + threadIdx.x) >> 5;
    int lane = threadIdx.x & 31;
    if (w >= NN) return;
    int hl = lane >> 3;
    int c0 = (lane & 7) << 3;

    float ad = head_sel(*(const float4*)(g_ad + 4 * (size_t)w), hl);

    float acc[8] = {};
    float den = 0.f;
    int beg = g_rowptr[w], end = g_rowptr[w + 1];
    const __half* xb = g_xl;

    for (int base = beg; base < end; base += 32) {
        int idx = base + lane;
        int sv = (idx < end) ? g_csrc[idx] : 0;
        int m = end - base; if (m > 32) m = 32;
        int j = 0;
        for (; j + 1 < m; j += 2) {
            int sA = __shfl_sync(0xFFFFFFFFu, sv, j);
            int sB = __shfl_sync(0xFFFFFFFFu, sv, j + 1);
            float4 aA = *(const float4*)(g_as + 4 * (size_t)sA);
            float4 aB = *(const float4*)(g_as + 4 * (size_t)sB);
            float4 xA = *(const float4*)(xb + (size_t)sA * HK + (lane << 3));
            float4 xB = *(const float4*)(xb + (size_t)sB * HK + (lane << 3));
            float eA = head_sel(aA, hl) + ad;
            float eB = head_sel(aB, hl) + ad;
            eA = eA > 0.f ? eA : 0.2f * eA;
            eB = eB > 0.f ? eB : 0.2f * eB;
            float pA = __expf(eA), pB = __expf(eB);
            den += pA + pB;
            __half2* hA = (__half2*)&xA;
            __half2* hB = (__half2*)&xB;
            #pragma unroll
            for (int q = 0; q < 4; q++) {
                float2 fA = __half22float2(hA[q]);
                float2 fB = __half22float2(hB[q]);
                acc[2 * q + 0] += pA * fA.x + pB * fB.x;
                acc[2 * q + 1] += pA * fA.y + pB * fB.y;
            }
        }
        if (j < m) {
            int s = __shfl_sync(0xFFFFFFFFu, sv, j);
            float4 a4 = *(const float4*)(g_as + 4 * (size_t)s);
            float4 x4 = *(const float4*)(xb + (size_t)s * HK + (lane << 3));
            float e = head_sel(a4, hl) + ad;
            e = e > 0.f ? e : 0.2f * e;
            float p = __expf(e);
            den += p;
            __half2* hx = (__half2*)&x4;
            #pragma unroll
            for (int q = 0; q < 4; q++) {
                float2 f = __half22float2(hx[q]);
                acc[2 * q + 0] += p * f.x;
                acc[2 * q + 1] += p * f.y;
            }
        }
    }

    float inv = 1.f / (den + 1e-16f);
    const float* gb = gat_b + layer * HID + c0;
    #pragma unroll
    for (int j = 0; j < 8; j++) {
        float v = acc[j] * inv;
        v += __shfl_xor_sync(0xFFFFFFFFu, v, 8);
        v += __shfl_xor_sync(0xFFFFFFFFu, v, 16);
        acc[j] = 0.25f * v + gb[j];
    }

    float sum = 0.f, sq = 0.f;
    #pragma unroll
    for (int j = 0; j < 8; j++) { sum += acc[j]; sq += acc[j] * acc[j]; }
    #pragma unroll
    for (int s = 1; s < 8; s <<= 1) {
        sum += __shfl_xor_sync(0xFFFFFFFFu, sum, s);
        sq  += __shfl_xor_sync(0xFFFFFFFFu, sq, s);
    }
    float mu   = sum * (1.f / 64.f);
    float var  = sq * (1.f / 64.f) - mu * mu;
    float rstd = rsqrtf(var + 1e-5f);

    float4 g0 = *(const float4*)(ln_g + layer * HID + c0);
    float4 g1 = *(const float4*)(ln_g + layer * HID + c0 + 4);
    float4 b0 = *(const float4*)(ln_b + layer * HID + c0);
    float4 b1 = *(const float4*)(ln_b + layer * HID + c0 + 4);
    float gg[8] = {g0.x, g0.y, g0.z, g0.w, g1.x, g1.y, g1.z, g1.w};
    float bv[8] = {b0.x, b0.y, b0.z, b0.w, b1.x, b1.y, b1.z, b1.w};

    float* hp = g_h + (size_t)w * HID + c0;
    float res[8] = {};
    if (layer > 0) {
        float4 r0 = *(const float4*)hp;
        float4 r1 = *(const float4*)(hp + 4);
        res[0] = r0.x; res[1] = r0.y; res[2] = r0.z; res[3] = r0.w;
        res[4] = r1.x; res[5] = r1.y; res[6] = r1.z; res[7] = r1.w;
    }
    float out[8];
    #pragma unroll
    for (int j = 0; j < 8; j++) {
        float v = (acc[j] - mu) * rstd * gg[j] + bv[j];
        v = v > 0.f ? v : expm1f(v);
        out[j] = v + res[j];
    }
    if (lane < 8) {
        *(float4*)hp       = make_float4(out[0], out[1], out[2], out[3]);
        *(float4*)(hp + 4) = make_float4(out[4], out[5], out[6], out[7]);
        __half2 h2[4];
        h2[0] = __floats2half2_rn(out[0], out[1]);
        h2[1] = __floats2half2_rn(out[2], out[3]);
        h2[2] = __floats2half2_rn(out[4], out[5]);
        h2[3] = __floats2half2_rn(out[6], out[7]);
        *(uint4*)(g_hh + (size_t)w * HID + c0) = *(uint4*)h2;
    }
}

// ---------------- host orchestration ----------------
extern "C" void kernel_launch(void* const* d_in, const int* in_sizes, int n_in,
                              void* d_out, int out_size) {
    const float* x       = (const float*)d_in[0];
    const int*   ei      = (const int*)d_in[1];
    const float* Wi      = (const float*)d_in[2];
    const float* bi      = (const float*)d_in[3];
    const float* lin_W   = (const float*)d_in[4];
    const float* att_src = (const float*)d_in[5];
    const float* att_dst = (const float*)d_in[6];
    const float* gat_b   = (const float*)d_in[7];
    const float* ln_g    = (const float*)d_in[8];
    const float* ln_b    = (const float*)d_in[9];
    const float* Wo      = (const float*)d_in[10];
    const float* bo      = (const float*)d_in[11];
    float* out = (float*)d_out;

    static bool inited = false;
    static float *p_h;
    static int *p_deg, *p_rowptr, *p_cursor;
    if (!inited) {
        cudaGetSymbolAddress((void**)&p_h, g_h);
        cudaGetSymbolAddress((void**)&p_deg, g_deg);
        cudaGetSymbolAddress((void**)&p_rowptr, g_rowptr);
        cudaGetSymbolAddress((void**)&p_cursor, g_cursor);
        inited = true;
    }

    const int EB = (ETOT + 255) / 256;
    const int MB = (NN + 127) / 128;

    cudaMemsetAsync(p_deg, 0, NN * sizeof(int));
    hist_kernel<<<EB, 256>>>(ei);
    att_proj_kernel<<<8, 256>>>(lin_W, att_src, att_dst);
    scan_kernel<<<1, 1024>>>();
    cudaMemcpyAsync(p_cursor, p_rowptr, NN * sizeof(int), cudaMemcpyDeviceToDevice);
    scatter_kernel<<<EB, 256>>>(ei);

    gemm128<<<dim3(1, MB), 256>>>(x, Wi, bi, p_h, NN, INC, HID, 1);

    for (int l = 0; l < NLAY; l++) {
        gemm_mma<<<dim3(NH, MB), 256>>>(lin_W, l);
        alpha2_kernel<<<(NN + 255) / 256, 256>>>(l);
        agg_fused<<<(NN + 7) / 8, 256>>>(gat_b, ln_g, ln_b, l);
    }

    gemm128<<<dim3(1, MB), 256>>>(p_h, Wo, bo, out, NN, HID, OUTC, 0);
}

// round 5
// speedup vs baseline: 2.4041x; 1.1310x over previous
#include <cuda_runtime.h>
#include <cuda_fp16.h>
#include <cmath>
#include <cstdint>

#define NN   50000
#define EE   800000
#define ETOT 850000
#define INC  128
#define HID  64
#define NH   4
#define HK   256
#define OUTC 40
#define NLAY 4

// ---------------- device scratch ----------------
__device__ float  g_h[(size_t)NN * HID];
__device__ __half g_hh[(size_t)NN * HID];     // half mirror of h
__device__ __half g_agg[(size_t)NN * HK];     // per-head aggregated h [N, 4*64]
__device__ float  g_as[(size_t)NN * NH];
__device__ float  g_ad[(size_t)NN * NH];
__device__ float  g_wa[NLAY * 8 * HID];       // projected attention vectors
__device__ __half g_wc[NLAY * NH * HID * HID];// 0.25 * W_h blocks, half, k-major
__device__ int    g_deg[NN];
__device__ int    g_rowptr[NN + 1];
__device__ int    g_cursor[NN];
__device__ int    g_csrc[ETOT];

// ---------------- CSR build (4 edges per thread for atomic MLP) ----------------
__global__ void hist_kernel(const int* __restrict__ ei) {
    int e0 = (blockIdx.x * blockDim.x + threadIdx.x) * 4;
    #pragma unroll
    for (int k = 0; k < 4; k++) {
        int e = e0 + k;
        if (e >= ETOT) return;
        int d = (e < EE) ? ei[EE + e] : (e - EE);
        atomicAdd(&g_deg[d], 1);
    }
}

__global__ void scan_kernel() {
    __shared__ int wsum[32];
    __shared__ int carry;
    int t = threadIdx.x;
    if (t == 0) carry = 0;
    __syncthreads();
    for (int base = 0; base < NN; base += 4096) {
        int i0 = base + t * 4;
        int4 v = make_int4(0, 0, 0, 0);
        if (i0 + 3 < NN) v = *(const int4*)(g_deg + i0);
        else {
            if (i0 + 0 < NN) v.x = g_deg[i0 + 0];
            if (i0 + 1 < NN) v.y = g_deg[i0 + 1];
            if (i0 + 2 < NN) v.z = g_deg[i0 + 2];
            if (i0 + 3 < NN) v.w = g_deg[i0 + 3];
        }
        int tot = v.x + v.y + v.z + v.w;
        int x = tot;
        #pragma unroll
        for (int s = 1; s < 32; s <<= 1) {
            int y = __shfl_up_sync(0xFFFFFFFFu, x, s);
            if ((t & 31) >= s) x += y;
        }
        if ((t & 31) == 31) wsum[t >> 5] = x;
        __syncthreads();
        if (t < 32) {
            int y = wsum[t];
            #pragma unroll
            for (int s = 1; s < 32; s <<= 1) {
                int z = __shfl_up_sync(0xFFFFFFFFu, y, s);
                if (t >= s) y += z;
            }
            wsum[t] = y;
        }
        __syncthreads();
        int excl = carry + x - tot + ((t >= 32) ? wsum[(t >> 5) - 1] : 0);
        if (i0 + 3 < NN) {
            *(int4*)(g_rowptr + i0) =
                make_int4(excl, excl + v.x, excl + v.x + v.y, excl + v.x + v.y + v.z);
        } else {
            if (i0 + 0 < NN) g_rowptr[i0 + 0] = excl;
            if (i0 + 1 < NN) g_rowptr[i0 + 1] = excl + v.x;
            if (i0 + 2 < NN) g_rowptr[i0 + 2] = excl + v.x + v.y;
            if (i0 + 3 < NN) g_rowptr[i0 + 3] = excl + v.x + v.y + v.z;
        }
        __syncthreads();
        if (t == 0) carry += wsum[31];
        __syncthreads();
    }
    if (t == 0) g_rowptr[NN] = carry;
}

__global__ void scatter_kernel(const int* __restrict__ ei) {
    int e0 = (blockIdx.x * blockDim.x + threadIdx.x) * 4;
    #pragma unroll
    for (int k = 0; k < 4; k++) {
        int e = e0 + k;
        if (e >= ETOT) return;
        int s, d;
        if (e < EE) { s = ei[e]; d = ei[EE + e]; } else { s = d = e - EE; }
        int pos = atomicAdd(&g_cursor[d], 1);
        g_csrc[pos] = s;
    }
}

// ---------------- weight preprocessing ----------------
__global__ void att_proj_kernel(const float* __restrict__ lin_W,
                                const float* __restrict__ att_src,
                                const float* __restrict__ att_dst) {
    int tid = blockIdx.x * blockDim.x + threadIdx.x;
    if (tid >= NLAY * 8 * HID) return;
    int k = tid & 63;
    int v = (tid >> 6) & 7;
    int l = tid >> 9;
    int h = v & 3;
    const float* att  = (v < 4) ? att_src : att_dst;
    const float* wrow = lin_W + (size_t)l * HID * HK + (size_t)k * HK + h * HID;
    const float* arow = att + l * HK + h * HID;
    float s = 0.f;
    #pragma unroll
    for (int c = 0; c < HID; c++) s += wrow[c] * arow[c];
    g_wa[tid] = s;
}

// g_wc[((l*4+h)*64 + k)*64 + c] = 0.25 * lin_W[l][k][h*64+c]
__global__ void wcat_kernel(const float* __restrict__ lin_W) {
    int tid = blockIdx.x * blockDim.x + threadIdx.x;
    if (tid >= NLAY * NH * HID * HID) return;
    int c = tid & 63;
    int k = (tid >> 6) & 63;
    int h = (tid >> 12) & 3;
    int l = tid >> 14;
    g_wc[tid] = __float2half(0.25f * lin_W[(size_t)l * HID * HK + (size_t)k * HK + h * HID + c]);
}

// ---------------- fp32 GEMM (input / output layers) ----------------
__global__ void gemm128(const float* __restrict__ A, const float* __restrict__ B,
                        const float* __restrict__ bias, void* __restrict__ Cv,
                        int M, int K, int Nc, int mode) {
    __shared__ float As[16][132];
    __shared__ float Bs[16][72];
    int t  = threadIdx.x;
    int tx = t & 15, ty = t >> 4;
    int m0 = blockIdx.y << 7;
    int n0 = blockIdx.x << 6;
    float acc[8][4] = {};

    for (int k0 = 0; k0 < K; k0 += 16) {
        #pragma unroll
        for (int i = 0; i < 2; i++) {
            int idx = t + i * 256;
            int row = idx >> 2;
            int kc  = (idx & 3) << 2;
            float4 av = make_float4(0.f, 0.f, 0.f, 0.f);
            if (m0 + row < M)
                av = *(const float4*)(A + (size_t)(m0 + row) * K + k0 + kc);
            As[kc + 0][row] = av.x; As[kc + 1][row] = av.y;
            As[kc + 2][row] = av.z; As[kc + 3][row] = av.w;
        }
        {
            int bk = t >> 4, bn = (t & 15) << 2;
            const float* bp = B + (size_t)(k0 + bk) * Nc + n0 + bn;
            float4 bv = make_float4(0.f, 0.f, 0.f, 0.f);
            if (n0 + bn + 3 < Nc) bv = *(const float4*)bp;
            else {
                if (n0 + bn + 0 < Nc) bv.x = bp[0];
                if (n0 + bn + 1 < Nc) bv.y = bp[1];
                if (n0 + bn + 2 < Nc) bv.z = bp[2];
            }
            *(float4*)&Bs[bk][bn] = bv;
        }
        __syncthreads();

        #pragma unroll
        for (int kk = 0; kk < 16; kk++) {
            float4 a0 = *(const float4*)&As[kk][ty << 3];
            float4 a1 = *(const float4*)&As[kk][(ty << 3) + 4];
            float4 b  = *(const float4*)&Bs[kk][tx << 2];
            float av[8] = {a0.x, a0.y, a0.z, a0.w, a1.x, a1.y, a1.z, a1.w};
            #pragma unroll
            for (int i = 0; i < 8; i++) {
                acc[i][0] += av[i] * b.x;
                acc[i][1] += av[i] * b.y;
                acc[i][2] += av[i] * b.z;
                acc[i][3] += av[i] * b.w;
            }
        }
        __syncthreads();
    }

    float bb[4] = {0.f, 0.f, 0.f, 0.f};
    if (bias) {
        #pragma unroll
        for (int j = 0; j < 4; j++) {
            int c = n0 + (tx << 2) + j;
            if (c < Nc) bb[j] = bias[c];
        }
    }
    #pragma unroll
    for (int i = 0; i < 8; i++) {
        int r = m0 + (ty << 3) + i;
        if (r >= M) continue;
        int c = n0 + (tx << 2);
        float v0 = acc[i][0] + bb[0], v1 = acc[i][1] + bb[1];
        float v2 = acc[i][2] + bb[2], v3 = acc[i][3] + bb[3];
        if (mode == 1) {
            v0 = v0 > 0.f ? v0 : expm1f(v0);
            v1 = v1 > 0.f ? v1 : expm1f(v1);
            v2 = v2 > 0.f ? v2 : expm1f(v2);
            v3 = v3 > 0.f ? v3 : expm1f(v3);
        }
        float* cf = (float*)Cv + (size_t)r * Nc + c;
        if (c + 3 < Nc) {
            *(float4*)cf = make_float4(v0, v1, v2, v3);
        } else {
            if (c + 0 < Nc) cf[0] = v0;
            if (c + 1 < Nc) cf[1] = v1;
            if (c + 2 < Nc) cf[2] = v2;
        }
        if (mode == 1) {
            __half2* hp = (__half2*)(g_hh + (size_t)r * HID + c);
            hp[0] = __floats2half2_rn(v0, v1);
            hp[1] = __floats2half2_rn(v2, v3);
        }
    }
}

// ---------------- alphas from g_hh and projected vectors ----------------
__global__ void alpha2_kernel(int layer) {
    __shared__ float wa[8][64];
    int t = threadIdx.x;
    #pragma unroll
    for (int i = 0; i < 2; i++)
        ((float*)wa)[t + i * 256] = g_wa[layer * 512 + t + i * 256];
    __syncthreads();
    int n = blockIdx.x * 256 + t;
    if (n >= NN) return;
    const uint4* hp = (const uint4*)(g_hh + (size_t)n * HID);
    float r[8] = {};
    #pragma unroll
    for (int cc = 0; cc < 8; cc++) {
        uint4 raw = hp[cc];
        __half2* h2 = (__half2*)&raw;
        float f[8];
        float2 t0 = __half22float2(h2[0]); f[0] = t0.x; f[1] = t0.y;
        float2 t1 = __half22float2(h2[1]); f[2] = t1.x; f[3] = t1.y;
        float2 t2 = __half22float2(h2[2]); f[4] = t2.x; f[5] = t2.y;
        float2 t3 = __half22float2(h2[3]); f[6] = t3.x; f[7] = t3.y;
        #pragma unroll
        for (int v = 0; v < 8; v++) {
            #pragma unroll
            for (int j = 0; j < 8; j++)
                r[v] += f[j] * wa[v][cc * 8 + j];
        }
    }
    *(float4*)(g_as + 4 * (size_t)n) = make_float4(r[0], r[1], r[2], r[3]);
    *(float4*)(g_ad + 4 * (size_t)n) = make_float4(r[4], r[5], r[6], r[7]);
}

// ---------------- aggregation in h-space: agg[n,h,:] = softmax-weighted sum of h[s] ----------------
__global__ void agg_h_kernel() {
    int w    = (blockIdx.x * blockDim.x + threadIdx.x) >> 5;
    int lane = threadIdx.x & 31;
    if (w >= NN) return;

    float4 ad4 = *(const float4*)(g_ad + 4 * (size_t)w);

    float acc[4][2] = {};
    float denl[4] = {};
    int beg = g_rowptr[w], end = g_rowptr[w + 1];

    for (int base = beg; base < end; base += 32) {
        int idx = base + lane;
        bool valid = idx < end;
        int sv = valid ? g_csrc[idx] : 0;
        // own-edge softmax weights (one exp set per edge, computed by owning lane)
        float4 as4 = *(const float4*)(g_as + 4 * (size_t)sv);
        float p[4];
        {
            float e0 = as4.x + ad4.x, e1 = as4.y + ad4.y;
            float e2 = as4.z + ad4.z, e3 = as4.w + ad4.w;
            e0 = e0 > 0.f ? e0 : 0.2f * e0;
            e1 = e1 > 0.f ? e1 : 0.2f * e1;
            e2 = e2 > 0.f ? e2 : 0.2f * e2;
            e3 = e3 > 0.f ? e3 : 0.2f * e3;
            p[0] = valid ? __expf(e0) : 0.f;
            p[1] = valid ? __expf(e1) : 0.f;
            p[2] = valid ? __expf(e2) : 0.f;
            p[3] = valid ? __expf(e3) : 0.f;
        }
        denl[0] += p[0]; denl[1] += p[1]; denl[2] += p[2]; denl[3] += p[3];

        int m = end - base; if (m > 32) m = 32;
        for (int j = 0; j < m; j++) {
            int   s  = __shfl_sync(0xFFFFFFFFu, sv,  j);
            float p0 = __shfl_sync(0xFFFFFFFFu, p[0], j);
            float p1 = __shfl_sync(0xFFFFFFFFu, p[1], j);
            float p2 = __shfl_sync(0xFFFFFFFFu, p[2], j);
            float p3 = __shfl_sync(0xFFFFFFFFu, p[3], j);
            // gather 2 channels of h[s] per lane (coalesced 128B per warp)
            __half2 hv = *(const __half2*)(g_hh + (size_t)s * HID + 2 * lane);
            float2 f = __half22float2(hv);
            acc[0][0] += p0 * f.x; acc[0][1] += p0 * f.y;
            acc[1][0] += p1 * f.x; acc[1][1] += p1 * f.y;
            acc[2][0] += p2 * f.x; acc[2][1] += p2 * f.y;
            acc[3][0] += p3 * f.x; acc[3][1] += p3 * f.y;
        }
    }

    // warp-reduce denominators
    #pragma unroll
    for (int h = 0; h < 4; h++) {
        float d = denl[h];
        #pragma unroll
        for (int s = 16; s > 0; s >>= 1)
            d += __shfl_xor_sync(0xFFFFFFFFu, d, s);
        denl[h] = 1.f / (d + 1e-16f);
    }

    __half* ap = g_agg + (size_t)w * HK;
    #pragma unroll
    for (int h = 0; h < 4; h++) {
        *(__half2*)(ap + h * HID + 2 * lane) =
            __floats2half2_rn(acc[h][0] * denl[h], acc[h][1] * denl[h]);
    }
}

// ---------------- MMA head-mix GEMM + fused bias/LN/ELU/residual epilogue ----------------
// C[m, c] = sum_h agg[m, h*64:h*64+64] @ (0.25*W_h)[64, c]; then epilogue -> g_h, g_hh
__global__ void gemm_agg(const float* __restrict__ gat_b,
                         const float* __restrict__ ln_g,
                         const float* __restrict__ ln_b, int layer) {
    __shared__ alignas(16) char buf[34816];  // mainloop: A 16K + B 8K; epilogue: C 128x68 f32
    __half* Asm = (__half*)buf;              // 128 x 64
    __half* Bsm = (__half*)(buf + 16384);    // 64 x 64
    float*  Cs  = (float*)buf;               // 128 x 68

    int t  = threadIdx.x;
    int m0 = blockIdx.x << 7;
    int wid = t >> 5, lane = t & 31;
    int wm = (wid & 3) << 5;
    int wn = (wid >> 2) << 5;

    float c[2][4][4] = {};

    for (int h = 0; h < 4; h++) {
        if (h) __syncthreads();   // protect smem reuse across iterations
        // A: rows m0..m0+127, cols h*64..h*64+63 of g_agg
        #pragma unroll
        for (int i = 0; i < 4; i++) {
            int cid = t + i * 256;
            int r = cid >> 3, cc = cid & 7;
            uint4 v = make_uint4(0, 0, 0, 0);
            if (m0 + r < NN)
                v = *(const uint4*)(g_agg + (size_t)(m0 + r) * HK + h * HID + (cc << 3));
            *(uint4*)(Asm + r * 64 + ((cc ^ (r & 7)) << 3)) = v;
        }
        // B: 64x64 half from g_wc
        const __half* wb = g_wc + (size_t)(layer * 4 + h) * HID * HID;
        #pragma unroll
        for (int i = 0; i < 2; i++) {
            int cid = t + i * 256;
            int k = cid >> 3, cc = cid & 7;
            uint4 v = *(const uint4*)(wb + k * 64 + (cc << 3));
            *(uint4*)(Bsm + k * 64 + ((cc ^ (k & 7)) << 3)) = v;
        }
        __syncthreads();

        #pragma unroll
        for (int ks = 0; ks < 4; ks++) {
            uint32_t a[2][4];
            #pragma unroll
            for (int mt = 0; mt < 2; mt++) {
                int row = wm + (mt << 4) + (lane & 15);
                int chunk = (ks << 1) + (lane >> 4);
                uint32_t addr = (uint32_t)__cvta_generic_to_shared(
                    Asm + row * 64 + ((chunk ^ (row & 7)) << 3));
                asm volatile("ldmatrix.sync.aligned.m8n8.x4.shared.b16 {%0,%1,%2,%3}, [%4];"
                             : "=r"(a[mt][0]), "=r"(a[mt][1]), "=r"(a[mt][2]), "=r"(a[mt][3])
                             : "r"(addr));
            }
            uint32_t b[4][2];
            #pragma unroll
            for (int nt2 = 0; nt2 < 2; nt2++) {
                int krow = (ks << 4) + (lane & 15);
                int nchunk = ((wn + (nt2 << 4)) >> 3) + (lane >> 4);
                uint32_t addr = (uint32_t)__cvta_generic_to_shared(
                    Bsm + krow * 64 + ((nchunk ^ (krow & 7)) << 3));
                uint32_t r0, r1, r2, r3;
                asm volatile("ldmatrix.sync.aligned.m8n8.x4.trans.shared.b16 {%0,%1,%2,%3}, [%4];"
                             : "=r"(r0), "=r"(r1), "=r"(r2), "=r"(r3)
                             : "r"(addr));
                b[nt2 * 2 + 0][0] = r0; b[nt2 * 2 + 0][1] = r1;
                b[nt2 * 2 + 1][0] = r2; b[nt2 * 2 + 1][1] = r3;
            }
            #pragma unroll
            for (int mt = 0; mt < 2; mt++)
                #pragma unroll
                for (int nt = 0; nt < 4; nt++)
                    asm volatile(
                        "mma.sync.aligned.m16n8k16.row.col.f32.f16.f16.f32 "
                        "{%0,%1,%2,%3},{%4,%5,%6,%7},{%8,%9},{%0,%1,%2,%3};"
                        : "+f"(c[mt][nt][0]), "+f"(c[mt][nt][1]),
                          "+f"(c[mt][nt][2]), "+f"(c[mt][nt][3])
                        : "r"(a[mt][0]), "r"(a[mt][1]), "r"(a[mt][2]), "r"(a[mt][3]),
                          "r"(b[nt][0]), "r"(b[nt][1]));
        }
    }

    __syncthreads();  // done reading A/B smem
    // stage C to smem for row-wise LN
    int rg = lane >> 2, cg = (lane & 3) << 1;
    #pragma unroll
    for (int mt = 0; mt < 2; mt++) {
        int r = wm + (mt << 4) + rg;
        #pragma unroll
        for (int nt = 0; nt < 4; nt++) {
            int col = wn + (nt << 3) + cg;
            Cs[r * 68 + col]       = c[mt][nt][0];
            Cs[r * 68 + col + 1]   = c[mt][nt][1];
            Cs[(r + 8) * 68 + col]     = c[mt][nt][2];
            Cs[(r + 8) * 68 + col + 1] = c[mt][nt][3];
        }
    }
    __syncthreads();

    // epilogue: 16 rows per warp; each lane owns 2 channels
    float2 gbv = *(const float2*)(gat_b + layer * HID + 2 * lane);
    float2 ggv = *(const float2*)(ln_g  + layer * HID + 2 * lane);
    float2 lbv = *(const float2*)(ln_b  + layer * HID + 2 * lane);
    for (int rr = 0; rr < 16; rr++) {
        int r = wid * 16 + rr;
        int n = m0 + r;
        if (n >= NN) break;
        float v0 = Cs[r * 68 + 2 * lane]     + gbv.x;
        float v1 = Cs[r * 68 + 2 * lane + 1] + gbv.y;
        float sum = v0 + v1, sq = v0 * v0 + v1 * v1;
        #pragma unroll
        for (int s = 16; s > 0; s >>= 1) {
            sum += __shfl_xor_sync(0xFFFFFFFFu, sum, s);
            sq  += __shfl_xor_sync(0xFFFFFFFFu, sq, s);
        }
        float mu   = sum * (1.f / 64.f);
        float var  = sq * (1.f / 64.f) - mu * mu;
        float rstd = rsqrtf(var + 1e-5f);
        v0 = (v0 - mu) * rstd * ggv.x + lbv.x;
        v1 = (v1 - mu) * rstd * ggv.y + lbv.y;
        v0 = v0 > 0.f ? v0 : expm1f(v0);
        v1 = v1 > 0.f ? v1 : expm1f(v1);
        float* hp = g_h + (size_t)n * HID + 2 * lane;
        if (layer > 0) {
            float2 rv = *(const float2*)hp;
            v0 += rv.x; v1 += rv.y;
        }
        *(float2*)hp = make_float2(v0, v1);
        *(__half2*)(g_hh + (size_t)n * HID + 2 * lane) = __floats2half2_rn(v0, v1);
    }
}

// ---------------- host orchestration ----------------
extern "C" void kernel_launch(void* const* d_in, const int* in_sizes, int n_in,
                              void* d_out, int out_size) {
    const float* x       = (const float*)d_in[0];
    const int*   ei      = (const int*)d_in[1];
    const float* Wi      = (const float*)d_in[2];
    const float* bi      = (const float*)d_in[3];
    const float* lin_W   = (const float*)d_in[4];
    const float* att_src = (const float*)d_in[5];
    const float* att_dst = (const float*)d_in[6];
    const float* gat_b   = (const float*)d_in[7];
    const float* ln_g    = (const float*)d_in[8];
    const float* ln_b    = (const float*)d_in[9];
    const float* Wo      = (const float*)d_in[10];
    const float* bo      = (const float*)d_in[11];
    float* out = (float*)d_out;

    static bool inited = false;
    static float *p_h;
    static int *p_deg, *p_rowptr, *p_cursor;
    if (!inited) {
        cudaGetSymbolAddress((void**)&p_h, g_h);
        cudaGetSymbolAddress((void**)&p_deg, g_deg);
        cudaGetSymbolAddress((void**)&p_rowptr, g_rowptr);
        cudaGetSymbolAddress((void**)&p_cursor, g_cursor);
        inited = true;
    }

    const int EB4 = (ETOT + 1023) / 1024;
    const int MB  = (NN + 127) / 128;

    cudaMemsetAsync(p_deg, 0, NN * sizeof(int));
    hist_kernel<<<EB4, 256>>>(ei);
    att_proj_kernel<<<8, 256>>>(lin_W, att_src, att_dst);
    wcat_kernel<<<NLAY * NH * HID * HID / 256, 256>>>(lin_W);
    scan_kernel<<<1, 1024>>>();
    cudaMemcpyAsync(p_cursor, p_rowptr, NN * sizeof(int), cudaMemcpyDeviceToDevice);
    scatter_kernel<<<EB4, 256>>>(ei);

    gemm128<<<dim3(1, MB), 256>>>(x, Wi, bi, p_h, NN, INC, HID, 1);

    for (int l = 0; l < NLAY; l++) {
        alpha2_kernel<<<(NN + 255) / 256, 256>>>(l);
        agg_h_kernel<<<(NN + 7) / 8, 256>>>();
        gemm_agg<<<MB, 256>>>(gat_b, ln_g, ln_b, l);
    }

    gemm128<<<dim3(1, MB), 256>>>(p_h, Wo, bo, out, NN, HID, OUTC, 0);
}

// round 6
// speedup vs baseline: 2.9619x; 1.2320x over previous
#include <cuda_runtime.h>
#include <cuda_fp16.h>
#include <cmath>
#include <cstdint>

#define NN   50000
#define EE   800000
#define ETOT 850000
#define INC  128
#define HID  64
#define NH   4
#define HK   256
#define OUTC 40
#define NLAY 4
#define SB   13      // scan blocks: 13 * 4096 >= NN

// ---------------- device scratch ----------------
__device__ float  g_h[(size_t)NN * HID];
__device__ __half g_hh[(size_t)NN * HID];
__device__ __half g_xh[(size_t)NN * INC];      // half x
__device__ __half g_agg[(size_t)NN * HK];
__device__ float  g_as[(size_t)NN * NH];
__device__ float  g_ad[(size_t)NN * NH];
__device__ float  g_wa[NLAY * 8 * HID];
__device__ __half g_wc[NLAY * NH * HID * HID];
__device__ __half g_wih[INC * HID];            // Wi half
__device__ __half g_woh[HID * 64];             // Wo half, N padded to 64
__device__ int    g_deg[NN];
__device__ int    g_rowptr[NN + 1];
__device__ int    g_cursor[NN];
__device__ int    g_csrc[ETOT];
__device__ int    g_bsum[16];

// ---------------- CSR build ----------------
__global__ void hist_kernel(const int* __restrict__ ei) {
    int e0 = (blockIdx.x * blockDim.x + threadIdx.x) * 4;
    #pragma unroll
    for (int k = 0; k < 4; k++) {
        int e = e0 + k;
        if (e >= ETOT) return;
        int d = (e < EE) ? ei[EE + e] : (e - EE);
        atomicAdd(&g_deg[d], 1);
    }
}

// phase 1: per-block scan of 4096 elements, local-exclusive into rowptr, block sum out
__global__ void scan1_kernel() {
    __shared__ int wsum[32];
    int t = threadIdx.x;
    int i0 = blockIdx.x * 4096 + t * 4;
    int4 v = make_int4(0, 0, 0, 0);
    if (i0 + 3 < NN) v = *(const int4*)(g_deg + i0);
    else {
        if (i0 + 0 < NN) v.x = g_deg[i0 + 0];
        if (i0 + 1 < NN) v.y = g_deg[i0 + 1];
        if (i0 + 2 < NN) v.z = g_deg[i0 + 2];
        if (i0 + 3 < NN) v.w = g_deg[i0 + 3];
    }
    int tot = v.x + v.y + v.z + v.w;
    int x = tot;
    #pragma unroll
    for (int s = 1; s < 32; s <<= 1) {
        int y = __shfl_up_sync(0xFFFFFFFFu, x, s);
        if ((t & 31) >= s) x += y;
    }
    if ((t & 31) == 31) wsum[t >> 5] = x;
    __syncthreads();
    if (t < 32) {
        int y = wsum[t];
        #pragma unroll
        for (int s = 1; s < 32; s <<= 1) {
            int z = __shfl_up_sync(0xFFFFFFFFu, y, s);
            if (t >= s) y += z;
        }
        wsum[t] = y;
    }
    __syncthreads();
    int excl = x - tot + ((t >= 32) ? wsum[(t >> 5) - 1] : 0);
    if (i0 + 3 < NN) {
        *(int4*)(g_rowptr + i0) =
            make_int4(excl, excl + v.x, excl + v.x + v.y, excl + v.x + v.y + v.z);
    } else {
        if (i0 + 0 < NN) g_rowptr[i0 + 0] = excl;
        if (i0 + 1 < NN) g_rowptr[i0 + 1] = excl + v.x;
        if (i0 + 2 < NN) g_rowptr[i0 + 2] = excl + v.x + v.y;
        if (i0 + 3 < NN) g_rowptr[i0 + 3] = excl + v.x + v.y + v.z;
    }
    if (t == 0) g_bsum[blockIdx.x] = wsum[31];
}

// phase 2: exclusive scan of 13 block sums (one warp)
__global__ void scan2_kernel() {
    int t = threadIdx.x;
    int v = (t < SB) ? g_bsum[t] : 0;
    int x = v;
    #pragma unroll
    for (int s = 1; s < 32; s <<= 1) {
        int y = __shfl_up_sync(0xFFFFFFFFu, x, s);
        if (t >= s) x += y;
    }
    if (t < SB) g_bsum[t] = x - v;
    if (t == SB - 1) g_rowptr[NN] = x;
}

// phase 3: add block offsets, mirror into cursor
__global__ void scan3_kernel() {
    int t = threadIdx.x;
    int i0 = blockIdx.x * 4096 + t * 4;
    int off = g_bsum[blockIdx.x];
    if (i0 + 3 < NN) {
        int4 r = *(const int4*)(g_rowptr + i0);
        r.x += off; r.y += off; r.z += off; r.w += off;
        *(int4*)(g_rowptr + i0) = r;
        *(int4*)(g_cursor + i0) = r;
    } else {
        for (int k = 0; k < 4; k++) {
            if (i0 + k < NN) {
                int r = g_rowptr[i0 + k] + off;
                g_rowptr[i0 + k] = r;
                g_cursor[i0 + k] = r;
            }
        }
    }
}

__global__ void scatter_kernel(const int* __restrict__ ei) {
    int e0 = (blockIdx.x * blockDim.x + threadIdx.x) * 4;
    #pragma unroll
    for (int k = 0; k < 4; k++) {
        int e = e0 + k;
        if (e >= ETOT) return;
        int s, d;
        if (e < EE) { s = ei[e]; d = ei[EE + e]; } else { s = d = e - EE; }
        int pos = atomicAdd(&g_cursor[d], 1);
        g_csrc[pos] = s;
    }
}

// ---------------- conversions / weight prep ----------------
__global__ void x2h_kernel(const float* __restrict__ x) {
    int i = (blockIdx.x * blockDim.x + threadIdx.x) * 8;
    if (i >= NN * INC) return;
    float4 a = *(const float4*)(x + i);
    float4 b = *(const float4*)(x + i + 4);
    __half2 h[4];
    h[0] = __floats2half2_rn(a.x, a.y);
    h[1] = __floats2half2_rn(a.z, a.w);
    h[2] = __floats2half2_rn(b.x, b.y);
    h[3] = __floats2half2_rn(b.z, b.w);
    *(uint4*)(g_xh + i) = *(uint4*)h;
}

__global__ void wconv_kernel(const float* __restrict__ Wi, const float* __restrict__ Wo) {
    int t = blockIdx.x * blockDim.x + threadIdx.x;
    if (t < INC * HID) g_wih[t] = __float2half(Wi[t]);
    if (t < HID * 64) {
        int k = t >> 6, c = t & 63;
        g_woh[t] = __float2half(c < OUTC ? Wo[k * OUTC + c] : 0.f);
    }
}

__global__ void att_proj_kernel(const float* __restrict__ lin_W,
                                const float* __restrict__ att_src,
                                const float* __restrict__ att_dst) {
    int tid = blockIdx.x * blockDim.x + threadIdx.x;
    if (tid >= NLAY * 8 * HID) return;
    int k = tid & 63;
    int v = (tid >> 6) & 7;
    int l = tid >> 9;
    int h = v & 3;
    const float* att  = (v < 4) ? att_src : att_dst;
    const float* wrow = lin_W + (size_t)l * HID * HK + (size_t)k * HK + h * HID;
    const float* arow = att + l * HK + h * HID;
    float s = 0.f;
    #pragma unroll
    for (int c = 0; c < HID; c++) s += wrow[c] * arow[c];
    g_wa[tid] = s;
}

__global__ void wcat_kernel(const float* __restrict__ lin_W) {
    int tid = blockIdx.x * blockDim.x + threadIdx.x;
    if (tid >= NLAY * NH * HID * HID) return;
    int c = tid & 63;
    int k = (tid >> 6) & 63;
    int h = (tid >> 12) & 3;
    int l = tid >> 14;
    g_wc[tid] = __float2half(0.25f * lin_W[(size_t)l * HID * HK + (size_t)k * HK + h * HID + c]);
}

// ---------------- MMA input GEMM: h = elu(x @ Wi + bi), K=128 ----------------
__global__ void gemm_in(const float* __restrict__ bi) {
    __shared__ alignas(16) __half Asm[128 * 128];  // 32 KB
    __shared__ alignas(16) __half Bsm[128 * 64];   // 16 KB
    int t = threadIdx.x;
    int m0 = blockIdx.x << 7;
    // A: 128 rows x 16 chunks
    #pragma unroll
    for (int i = 0; i < 8; i++) {
        int cid = t + i * 256;
        int r = cid >> 4, c = cid & 15;
        uint4 v = make_uint4(0, 0, 0, 0);
        if (m0 + r < NN)
            v = *(const uint4*)(g_xh + (size_t)(m0 + r) * INC + (c << 3));
        *(uint4*)(Asm + r * 128 + ((c ^ (r & 7)) << 3)) = v;
    }
    // B: 128 k-rows x 8 chunks (already half)
    #pragma unroll
    for (int i = 0; i < 4; i++) {
        int cid = t + i * 256;
        int k = cid >> 3, c = cid & 7;
        uint4 v = *(const uint4*)(g_wih + k * 64 + (c << 3));
        *(uint4*)(Bsm + k * 64 + ((c ^ (k & 7)) << 3)) = v;
    }
    __syncthreads();

    int wid = t >> 5, lane = t & 31;
    int wm = (wid & 3) << 5;
    int wn = (wid >> 2) << 5;
    float c[2][4][4] = {};

    #pragma unroll
    for (int ks = 0; ks < 8; ks++) {
        uint32_t a[2][4];
        #pragma unroll
        for (int mt = 0; mt < 2; mt++) {
            int row = wm + (mt << 4) + (lane & 15);
            int chunk = (ks << 1) + (lane >> 4);
            uint32_t addr = (uint32_t)__cvta_generic_to_shared(
                Asm + row * 128 + ((chunk ^ (row & 7)) << 3));
            asm volatile("ldmatrix.sync.aligned.m8n8.x4.shared.b16 {%0,%1,%2,%3}, [%4];"
                         : "=r"(a[mt][0]), "=r"(a[mt][1]), "=r"(a[mt][2]), "=r"(a[mt][3])
                         : "r"(addr));
        }
        uint32_t b[4][2];
        #pragma unroll
        for (int nt2 = 0; nt2 < 2; nt2++) {
            int krow = (ks << 4) + (lane & 15);
            int nchunk = ((wn + (nt2 << 4)) >> 3) + (lane >> 4);
            uint32_t addr = (uint32_t)__cvta_generic_to_shared(
                Bsm + krow * 64 + ((nchunk ^ (krow & 7)) << 3));
            uint32_t r0, r1, r2, r3;
            asm volatile("ldmatrix.sync.aligned.m8n8.x4.trans.shared.b16 {%0,%1,%2,%3}, [%4];"
                         : "=r"(r0), "=r"(r1), "=r"(r2), "=r"(r3)
                         : "r"(addr));
            b[nt2 * 2 + 0][0] = r0; b[nt2 * 2 + 0][1] = r1;
            b[nt2 * 2 + 1][0] = r2; b[nt2 * 2 + 1][1] = r3;
        }
        #pragma unroll
        for (int mt = 0; mt < 2; mt++)
            #pragma unroll
            for (int nt = 0; nt < 4; nt++)
                asm volatile(
                    "mma.sync.aligned.m16n8k16.row.col.f32.f16.f16.f32 "
                    "{%0,%1,%2,%3},{%4,%5,%6,%7},{%8,%9},{%0,%1,%2,%3};"
                    : "+f"(c[mt][nt][0]), "+f"(c[mt][nt][1]),
                      "+f"(c[mt][nt][2]), "+f"(c[mt][nt][3])
                    : "r"(a[mt][0]), "r"(a[mt][1]), "r"(a[mt][2]), "r"(a[mt][3]),
                      "r"(b[nt][0]), "r"(b[nt][1]));
    }

    int rg = lane >> 2, cg = (lane & 3) << 1;
    #pragma unroll
    for (int nt = 0; nt < 4; nt++) {
        int col = wn + (nt << 3) + cg;
        float b0 = bi[col], b1 = bi[col + 1];
        #pragma unroll
        for (int mt = 0; mt < 2; mt++) {
            #pragma unroll
            for (int half_ = 0; half_ < 2; half_++) {
                int r = m0 + wm + (mt << 4) + rg + half_ * 8;
                if (r >= NN) continue;
                float v0 = c[mt][nt][half_ * 2 + 0] + b0;
                float v1 = c[mt][nt][half_ * 2 + 1] + b1;
                v0 = v0 > 0.f ? v0 : expm1f(v0);
                v1 = v1 > 0.f ? v1 : expm1f(v1);
                *(float2*)(g_h + (size_t)r * HID + col) = make_float2(v0, v1);
                *(__half2*)(g_hh + (size_t)r * HID + col) = __floats2half2_rn(v0, v1);
            }
        }
    }
}

// ---------------- MMA output GEMM: out = h @ Wo + bo, K=64, N=40(pad 64) ----------------
__global__ void gemm_out(const float* __restrict__ bo, float* __restrict__ out) {
    __shared__ alignas(16) __half Asm[128 * 64];
    __shared__ alignas(16) __half Bsm[64 * 64];
    int t = threadIdx.x;
    int m0 = blockIdx.x << 7;
    #pragma unroll
    for (int i = 0; i < 4; i++) {
        int cid = t + i * 256;
        int r = cid >> 3, c = cid & 7;
        uint4 v = make_uint4(0, 0, 0, 0);
        if (m0 + r < NN)
            v = *(const uint4*)(g_hh + (size_t)(m0 + r) * HID + (c << 3));
        *(uint4*)(Asm + r * 64 + ((c ^ (r & 7)) << 3)) = v;
    }
    #pragma unroll
    for (int i = 0; i < 2; i++) {
        int cid = t + i * 256;
        int k = cid >> 3, c = cid & 7;
        uint4 v = *(const uint4*)(g_woh + k * 64 + (c << 3));
        *(uint4*)(Bsm + k * 64 + ((c ^ (k & 7)) << 3)) = v;
    }
    __syncthreads();

    int wid = t >> 5, lane = t & 31;
    int wm = (wid & 3) << 5;
    int wn = (wid >> 2) << 5;
    float c[2][4][4] = {};

    #pragma unroll
    for (int ks = 0; ks < 4; ks++) {
        uint32_t a[2][4];
        #pragma unroll
        for (int mt = 0; mt < 2; mt++) {
            int row = wm + (mt << 4) + (lane & 15);
            int chunk = (ks << 1) + (lane >> 4);
            uint32_t addr = (uint32_t)__cvta_generic_to_shared(
                Asm + row * 64 + ((chunk ^ (row & 7)) << 3));
            asm volatile("ldmatrix.sync.aligned.m8n8.x4.shared.b16 {%0,%1,%2,%3}, [%4];"
                         : "=r"(a[mt][0]), "=r"(a[mt][1]), "=r"(a[mt][2]), "=r"(a[mt][3])
                         : "r"(addr));
        }
        uint32_t b[4][2];
        #pragma unroll
        for (int nt2 = 0; nt2 < 2; nt2++) {
            int krow = (ks << 4) + (lane & 15);
            int nchunk = ((wn + (nt2 << 4)) >> 3) + (lane >> 4);
            uint32_t addr = (uint32_t)__cvta_generic_to_shared(
                Bsm + krow * 64 + ((nchunk ^ (krow & 7)) << 3));
            uint32_t r0, r1, r2, r3;
            asm volatile("ldmatrix.sync.aligned.m8n8.x4.trans.shared.b16 {%0,%1,%2,%3}, [%4];"
                         : "=r"(r0), "=r"(r1), "=r"(r2), "=r"(r3)
                         : "r"(addr));
            b[nt2 * 2 + 0][0] = r0; b[nt2 * 2 + 0][1] = r1;
            b[nt2 * 2 + 1][0] = r2; b[nt2 * 2 + 1][1] = r3;
        }
        #pragma unroll
        for (int mt = 0; mt < 2; mt++)
            #pragma unroll
            for (int nt = 0; nt < 4; nt++)
                asm volatile(
                    "mma.sync.aligned.m16n8k16.row.col.f32.f16.f16.f32 "
                    "{%0,%1,%2,%3},{%4,%5,%6,%7},{%8,%9},{%0,%1,%2,%3};"
                    : "+f"(c[mt][nt][0]), "+f"(c[mt][nt][1]),
                      "+f"(c[mt][nt][2]), "+f"(c[mt][nt][3])
                    : "r"(a[mt][0]), "r"(a[mt][1]), "r"(a[mt][2]), "r"(a[mt][3]),
                      "r"(b[nt][0]), "r"(b[nt][1]));
    }

    int rg = lane >> 2, cg = (lane & 3) << 1;
    #pragma unroll
    for (int nt = 0; nt < 4; nt++) {
        int col = wn + (nt << 3) + cg;
        if (col >= OUTC) continue;
        float b0 = bo[col], b1 = bo[col + 1];
        #pragma unroll
        for (int mt = 0; mt < 2; mt++) {
            #pragma unroll
            for (int half_ = 0; half_ < 2; half_++) {
                int r = m0 + wm + (mt << 4) + rg + half_ * 8;
                if (r >= NN) continue;
                *(float2*)(out + (size_t)r * OUTC + col) =
                    make_float2(c[mt][nt][half_ * 2 + 0] + b0,
                                c[mt][nt][half_ * 2 + 1] + b1);
            }
        }
    }
}

// ---------------- alphas from g_hh and projected vectors ----------------
__global__ void alpha2_kernel(int layer) {
    __shared__ float wa[8][64];
    int t = threadIdx.x;
    #pragma unroll
    for (int i = 0; i < 2; i++)
        ((float*)wa)[t + i * 256] = g_wa[layer * 512 + t + i * 256];
    __syncthreads();
    int n = blockIdx.x * 256 + t;
    if (n >= NN) return;
    const uint4* hp = (const uint4*)(g_hh + (size_t)n * HID);
    float r[8] = {};
    #pragma unroll
    for (int cc = 0; cc < 8; cc++) {
        uint4 raw = hp[cc];
        __half2* h2 = (__half2*)&raw;
        float f[8];
        float2 t0 = __half22float2(h2[0]); f[0] = t0.x; f[1] = t0.y;
        float2 t1 = __half22float2(h2[1]); f[2] = t1.x; f[3] = t1.y;
        float2 t2 = __half22float2(h2[2]); f[4] = t2.x; f[5] = t2.y;
        float2 t3 = __half22float2(h2[3]); f[6] = t3.x; f[7] = t3.y;
        #pragma unroll
        for (int v = 0; v < 8; v++) {
            #pragma unroll
            for (int j = 0; j < 8; j++)
                r[v] += f[j] * wa[v][cc * 8 + j];
        }
    }
    *(float4*)(g_as + 4 * (size_t)n) = make_float4(r[0], r[1], r[2], r[3]);
    *(float4*)(g_ad + 4 * (size_t)n) = make_float4(r[4], r[5], r[6], r[7]);
}

// ---------------- aggregation in h-space ----------------
__global__ void agg_h_kernel() {
    __shared__ float sp[8][32][4];
    int wl   = threadIdx.x >> 5;
    int w    = (blockIdx.x * blockDim.x + threadIdx.x) >> 5;
    int lane = threadIdx.x & 31;
    if (w >= NN) return;

    float4 ad4 = *(const float4*)(g_ad + 4 * (size_t)w);

    float acc[4][2] = {};
    float denl[4] = {};
    int beg = g_rowptr[w], end = g_rowptr[w + 1];

    for (int base = beg; base < end; base += 32) {
        int idx = base + lane;
        bool valid = idx < end;
        int sv = valid ? g_csrc[idx] : 0;
        float4 as4 = *(const float4*)(g_as + 4 * (size_t)sv);
        float p0, p1, p2, p3;
        {
            float e0 = as4.x + ad4.x, e1 = as4.y + ad4.y;
            float e2 = as4.z + ad4.z, e3 = as4.w + ad4.w;
            e0 = e0 > 0.f ? e0 : 0.2f * e0;
            e1 = e1 > 0.f ? e1 : 0.2f * e1;
            e2 = e2 > 0.f ? e2 : 0.2f * e2;
            e3 = e3 > 0.f ? e3 : 0.2f * e3;
            p0 = valid ? __expf(e0) : 0.f;
            p1 = valid ? __expf(e1) : 0.f;
            p2 = valid ? __expf(e2) : 0.f;
            p3 = valid ? __expf(e3) : 0.f;
        }
        denl[0] += p0; denl[1] += p1; denl[2] += p2; denl[3] += p3;
        *(float4*)&sp[wl][lane][0] = make_float4(p0, p1, p2, p3);
        __syncwarp();

        int m = end - base; if (m > 32) m = 32;
        int j = 0;
        for (; j + 1 < m; j += 2) {
            int sA = __shfl_sync(0xFFFFFFFFu, sv, j);
            int sB = __shfl_sync(0xFFFFFFFFu, sv, j + 1);
            float4 pA = *(const float4*)&sp[wl][j][0];
            float4 pB = *(const float4*)&sp[wl][j + 1][0];
            __half2 hA = *(const __half2*)(g_hh + (size_t)sA * HID + 2 * lane);
            __half2 hB = *(const __half2*)(g_hh + (size_t)sB * HID + 2 * lane);
            float2 fA = __half22float2(hA);
            float2 fB = __half22float2(hB);
            acc[0][0] += pA.x * fA.x + pB.x * fB.x;
            acc[0][1] += pA.x * fA.y + pB.x * fB.y;
            acc[1][0] += pA.y * fA.x + pB.y * fB.x;
            acc[1][1] += pA.y * fA.y + pB.y * fB.y;
            acc[2][0] += pA.z * fA.x + pB.z * fB.x;
            acc[2][1] += pA.z * fA.y + pB.z * fB.y;
            acc[3][0] += pA.w * fA.x + pB.w * fB.x;
            acc[3][1] += pA.w * fA.y + pB.w * fB.y;
        }
        if (j < m) {
            int s = __shfl_sync(0xFFFFFFFFu, sv, j);
            float4 pj = *(const float4*)&sp[wl][j][0];
            __half2 hv = *(const __half2*)(g_hh + (size_t)s * HID + 2 * lane);
            float2 f = __half22float2(hv);
            acc[0][0] += pj.x * f.x; acc[0][1] += pj.x * f.y;
            acc[1][0] += pj.y * f.x; acc[1][1] += pj.y * f.y;
            acc[2][0] += pj.z * f.x; acc[2][1] += pj.z * f.y;
            acc[3][0] += pj.w * f.x; acc[3][1] += pj.w * f.y;
        }
        __syncwarp();
    }

    #pragma unroll
    for (int h = 0; h < 4; h++) {
        float d = denl[h];
        #pragma unroll
        for (int s = 16; s > 0; s >>= 1)
            d += __shfl_xor_sync(0xFFFFFFFFu, d, s);
        denl[h] = 1.f / (d + 1e-16f);
    }

    __half* ap = g_agg + (size_t)w * HK;
    #pragma unroll
    for (int h = 0; h < 4; h++) {
        *(__half2*)(ap + h * HID + 2 * lane) =
            __floats2half2_rn(acc[h][0] * denl[h], acc[h][1] * denl[h]);
    }
}

// ---------------- MMA head-mix GEMM + fused epilogue ----------------
__global__ void gemm_agg(const float* __restrict__ gat_b,
                         const float* __restrict__ ln_g,
                         const float* __restrict__ ln_b, int layer) {
    __shared__ alignas(16) char buf[34816];
    __half* Asm = (__half*)buf;
    __half* Bsm = (__half*)(buf + 16384);
    float*  Cs  = (float*)buf;

    int t  = threadIdx.x;
    int m0 = blockIdx.x << 7;
    int wid = t >> 5, lane = t & 31;
    int wm = (wid & 3) << 5;
    int wn = (wid >> 2) << 5;

    float c[2][4][4] = {};

    for (int h = 0; h < 4; h++) {
        if (h) __syncthreads();
        #pragma unroll
        for (int i = 0; i < 4; i++) {
            int cid = t + i * 256;
            int r = cid >> 3, cc = cid & 7;
            uint4 v = make_uint4(0, 0, 0, 0);
            if (m0 + r < NN)
                v = *(const uint4*)(g_agg + (size_t)(m0 + r) * HK + h * HID + (cc << 3));
            *(uint4*)(Asm + r * 64 + ((cc ^ (r & 7)) << 3)) = v;
        }
        const __half* wb = g_wc + (size_t)(layer * 4 + h) * HID * HID;
        #pragma unroll
        for (int i = 0; i < 2; i++) {
            int cid = t + i * 256;
            int k = cid >> 3, cc = cid & 7;
            uint4 v = *(const uint4*)(wb + k * 64 + (cc << 3));
            *(uint4*)(Bsm + k * 64 + ((cc ^ (k & 7)) << 3)) = v;
        }
        __syncthreads();

        #pragma unroll
        for (int ks = 0; ks < 4; ks++) {
            uint32_t a[2][4];
            #pragma unroll
            for (int mt = 0; mt < 2; mt++) {
                int row = wm + (mt << 4) + (lane & 15);
                int chunk = (ks << 1) + (lane >> 4);
                uint32_t addr = (uint32_t)__cvta_generic_to_shared(
                    Asm + row * 64 + ((chunk ^ (row & 7)) << 3));
                asm volatile("ldmatrix.sync.aligned.m8n8.x4.shared.b16 {%0,%1,%2,%3}, [%4];"
                             : "=r"(a[mt][0]), "=r"(a[mt][1]), "=r"(a[mt][2]), "=r"(a[mt][3])
                             : "r"(addr));
            }
            uint32_t b[4][2];
            #pragma unroll
            for (int nt2 = 0; nt2 < 2; nt2++) {
                int krow = (ks << 4) + (lane & 15);
                int nchunk = ((wn + (nt2 << 4)) >> 3) + (lane >> 4);
                uint32_t addr = (uint32_t)__cvta_generic_to_shared(
                    Bsm + krow * 64 + ((nchunk ^ (krow & 7)) << 3));
                uint32_t r0, r1, r2, r3;
                asm volatile("ldmatrix.sync.aligned.m8n8.x4.trans.shared.b16 {%0,%1,%2,%3}, [%4];"
                             : "=r"(r0), "=r"(r1), "=r"(r2), "=r"(r3)
                             : "r"(addr));
                b[nt2 * 2 + 0][0] = r0; b[nt2 * 2 + 0][1] = r1;
                b[nt2 * 2 + 1][0] = r2; b[nt2 * 2 + 1][1] = r3;
            }
            #pragma unroll
            for (int mt = 0; mt < 2; mt++)
                #pragma unroll
                for (int nt = 0; nt < 4; nt++)
                    asm volatile(
                        "mma.sync.aligned.m16n8k16.row.col.f32.f16.f16.f32 "
                        "{%0,%1,%2,%3},{%4,%5,%6,%7},{%8,%9},{%0,%1,%2,%3};"
                        : "+f"(c[mt][nt][0]), "+f"(c[mt][nt][1]),
                          "+f"(c[mt][nt][2]), "+f"(c[mt][nt][3])
                        : "r"(a[mt][0]), "r"(a[mt][1]), "r"(a[mt][2]), "r"(a[mt][3]),
                          "r"(b[nt][0]), "r"(b[nt][1]));
        }
    }

    __syncthreads();
    int rg = lane >> 2, cg = (lane & 3) << 1;
    #pragma unroll
    for (int mt = 0; mt < 2; mt++) {
        int r = wm + (mt << 4) + rg;
        #pragma unroll
        for (int nt = 0; nt < 4; nt++) {
            int col = wn + (nt << 3) + cg;
            Cs[r * 68 + col]       = c[mt][nt][0];
            Cs[r * 68 + col + 1]   = c[mt][nt][1];
            Cs[(r + 8) * 68 + col]     = c[mt][nt][2];
            Cs[(r + 8) * 68 + col + 1] = c[mt][nt][3];
        }
    }
    __syncthreads();

    float2 gbv = *(const float2*)(gat_b + layer * HID + 2 * lane);
    float2 ggv = *(const float2*)(ln_g  + layer * HID + 2 * lane);
    float2 lbv = *(const float2*)(ln_b  + layer * HID + 2 * lane);
    for (int rr = 0; rr < 16; rr++) {
        int r = wid * 16 + rr;
        int n = m0 + r;
        if (n >= NN) break;
        float v0 = Cs[r * 68 + 2 * lane]     + gbv.x;
        float v1 = Cs[r * 68 + 2 * lane + 1] + gbv.y;
        float sum = v0 + v1, sq = v0 * v0 + v1 * v1;
        #pragma unroll
        for (int s = 16; s > 0; s >>= 1) {
            sum += __shfl_xor_sync(0xFFFFFFFFu, sum, s);
            sq  += __shfl_xor_sync(0xFFFFFFFFu, sq, s);
        }
        float mu   = sum * (1.f / 64.f);
        float var  = sq * (1.f / 64.f) - mu * mu;
        float rstd = rsqrtf(var + 1e-5f);
        v0 = (v0 - mu) * rstd * ggv.x + lbv.x;
        v1 = (v1 - mu) * rstd * ggv.y + lbv.y;
        v0 = v0 > 0.f ? v0 : expm1f(v0);
        v1 = v1 > 0.f ? v1 : expm1f(v1);
        float* hp = g_h + (size_t)n * HID + 2 * lane;
        if (layer > 0) {
            float2 rv = *(const float2*)hp;
            v0 += rv.x; v1 += rv.y;
        }
        *(float2*)hp = make_float2(v0, v1);
        *(__half2*)(g_hh + (size_t)n * HID + 2 * lane) = __floats2half2_rn(v0, v1);
    }
}

// ---------------- host orchestration ----------------
extern "C" void kernel_launch(void* const* d_in, const int* in_sizes, int n_in,
                              void* d_out, int out_size) {
    const float* x       = (const float*)d_in[0];
    const int*   ei      = (const int*)d_in[1];
    const float* Wi      = (const float*)d_in[2];
    const float* bi      = (const float*)d_in[3];
    const float* lin_W   = (const float*)d_in[4];
    const float* att_src = (const float*)d_in[5];
    const float* att_dst = (const float*)d_in[6];
    const float* gat_b   = (const float*)d_in[7];
    const float* ln_g    = (const float*)d_in[8];
    const float* ln_b    = (const float*)d_in[9];
    const float* Wo      = (const float*)d_in[10];
    const float* bo      = (const float*)d_in[11];
    float* out = (float*)d_out;

    static bool inited = false;
    static int *p_deg;
    static cudaStream_t s1;
    static cudaEvent_t ev0, ev1;
    if (!inited) {
        cudaGetSymbolAddress((void**)&p_deg, g_deg);
        cudaStreamCreateWithFlags(&s1, cudaStreamNonBlocking);
        cudaEventCreateWithFlags(&ev0, cudaEventDisableTiming);
        cudaEventCreateWithFlags(&ev1, cudaEventDisableTiming);
        inited = true;
    }

    const int EB4 = (ETOT + 1023) / 1024;
    const int MB  = (NN + 127) / 128;

    // ---- fork: CSR chain on side stream ----
    cudaEventRecord(ev0, 0);
    cudaStreamWaitEvent(s1, ev0, 0);
    cudaMemsetAsync(p_deg, 0, NN * sizeof(int), s1);
    hist_kernel<<<EB4, 256, 0, s1>>>(ei);
    scan1_kernel<<<SB, 1024, 0, s1>>>();
    scan2_kernel<<<1, 32, 0, s1>>>();
    scan3_kernel<<<SB, 1024, 0, s1>>>();
    scatter_kernel<<<EB4, 256, 0, s1>>>(ei);
    cudaEventRecord(ev1, s1);

    // ---- main stream: conversions, weight prep, input GEMM, layer-0 alphas ----
    x2h_kernel<<<(NN * INC / 8 + 255) / 256, 256>>>(x);
    wconv_kernel<<<(INC * HID + 255) / 256, 256>>>(Wi, Wo);
    att_proj_kernel<<<8, 256>>>(lin_W, att_src, att_dst);
    wcat_kernel<<<NLAY * NH * HID * HID / 256, 256>>>(lin_W);
    gemm_in<<<MB, 256>>>(bi);
    alpha2_kernel<<<(NN + 255) / 256, 256>>>(0);

    // ---- join before first aggregation ----
    cudaStreamWaitEvent(0, ev1, 0);

    for (int l = 0; l < NLAY; l++) {
        agg_h_kernel<<<(NN + 7) / 8, 256>>>();
        gemm_agg<<<MB, 256>>>(gat_b, ln_g, ln_b, l);
        if (l + 1 < NLAY)
            alpha2_kernel<<<(NN + 255) / 256, 256>>>(l + 1);
    }

    gemm_out<<<MB, 256>>>(bo, out);
}